// round 13
// baseline (speedup 1.0000x reference)
#include <cuda_runtime.h>
#include <cuda_fp16.h>
#include <cstdint>

// Problem constants
#define BB   16
#define NT   4096
#define CC   768
#define HH   8
#define DD   96
#define MM   (BB * NT)          // 65536
#define GSZ  (768 * 768)        // 589824
#define KSPL 4                  // K-split for the G GEMM

// ---------------------------------------------------------------------------
// Scratch (__device__ globals)
// ---------------------------------------------------------------------------
__device__ __half g_xhi[(size_t)MM * CC];
__device__ __half g_xThi[(size_t)MM * CC], g_xTlo[(size_t)MM * CC]; // [b,c,n]
__device__ float g_Gpart[(size_t)BB * KSPL * 21 * 16384];           // fp32 partials
__device__ __half g_Ghi[BB * GSZ], g_Glo[BB * GSZ];
__device__ float g_T[BB * GSZ];
__device__ float g_attn[BB * HH * DD * DD];
__device__ __half g_MThi[BB * GSZ];                     // [b, c, h*96+d]
__device__ __half g_Phi[BB * GSZ];
__device__ __half g_wqh[GSZ], g_wql[GSZ];
__device__ __half g_wph[GSZ];
__device__ float g_s[BB * CC];
__device__ float g_part2[1024 * CC];                    // per-64-row-block colsums
__device__ float g_U[BB * 1536];
__device__ float g_r[BB * CC];
__device__ float g_biasf[BB * CC];

// ---------------------------------------------------------------------------
// PTX helpers (target-agnostic)
// ---------------------------------------------------------------------------
__device__ __forceinline__ uint32_t smem_u32(const void* p) {
    uint32_t a;
    asm("{ .reg .u64 t; cvta.to.shared.u64 t, %1; cvt.u32.u64 %0, t; }"
        : "=r"(a) : "l"(p));
    return a;
}
__device__ __forceinline__ void ldsm_x4(uint32_t* r, uint32_t addr) {
    asm volatile("ldmatrix.sync.aligned.m8n8.x4.shared.b16 {%0,%1,%2,%3}, [%4];"
                 : "=r"(r[0]), "=r"(r[1]), "=r"(r[2]), "=r"(r[3]) : "r"(addr));
}
__device__ __forceinline__ void mma16816(float* c, const uint32_t* a, const uint32_t* b) {
    asm volatile(
        "mma.sync.aligned.m16n8k16.row.col.f32.f16.f16.f32 "
        "{%0,%1,%2,%3}, {%4,%5,%6,%7}, {%8,%9}, {%0,%1,%2,%3};"
        : "+f"(c[0]), "+f"(c[1]), "+f"(c[2]), "+f"(c[3])
        : "r"(a[0]), "r"(a[1]), "r"(a[2]), "r"(a[3]), "r"(b[0]), "r"(b[1]));
}
__device__ __forceinline__ void cp16(uint32_t dst, const void* src) {
    asm volatile("cp.async.cg.shared.global [%0], [%1], 16;"
                 :: "r"(dst), "l"(src) : "memory");
}
__device__ __forceinline__ void cp_commit() {
    asm volatile("cp.async.commit_group;" ::: "memory");
}
template <int N>
__device__ __forceinline__ void cp_wait() {
    asm volatile("cp.async.wait_group %0;" :: "n"(N) : "memory");
}
__device__ __forceinline__ void split1(float v, __half& h, __half& l) {
    h = __float2half_rn(v);
    l = __float2half_rn(v - __half2float(h));
}
__device__ __forceinline__ ushort hfu(__half v) { return __half_as_ushort(v); }

// ---------------------------------------------------------------------------
// transpose_split: x -> row-major hi, per-batch transposed hi/lo,
// AND per-block column partial sums (fused colsum).
// ---------------------------------------------------------------------------
__global__ __launch_bounds__(256)
void transpose_split_kernel(const float* __restrict__ x)
{
    __shared__ float tile[64 * 65];
    __shared__ float colp[4][64];
    const int tid = threadIdx.x;
    const int C0 = blockIdx.x * 64;
    const int R0 = blockIdx.y * 64;

    #pragma unroll
    for (int t = 0; t < 4; ++t) {
        const int id = tid + t * 256;
        const int r = id >> 4, f4 = id & 15;
        float4 v = *(const float4*)(x + (size_t)(R0 + r) * CC + C0 + f4 * 4);
        tile[r * 65 + f4 * 4 + 0] = v.x;
        tile[r * 65 + f4 * 4 + 1] = v.y;
        tile[r * 65 + f4 * 4 + 2] = v.z;
        tile[r * 65 + f4 * 4 + 3] = v.w;
    }
    __syncthreads();

    {
        const int c = tid & 63, q = tid >> 6;
        float s = 0.f;
        #pragma unroll
        for (int r = 0; r < 16; ++r) s += tile[(q * 16 + r) * 65 + c];
        colp[q][c] = s;
    }
    __syncthreads();
    if (tid < 64)
        g_part2[(size_t)blockIdx.y * CC + C0 + tid] =
            colp[0][tid] + colp[1][tid] + colp[2][tid] + colp[3][tid];

    #pragma unroll
    for (int t = 0; t < 2; ++t) {
        const int id = tid + t * 256;
        const int r = id >> 3, g = id & 7;
        ushort h[8];
        #pragma unroll
        for (int j = 0; j < 8; j++)
            h[j] = hfu(__float2half_rn(tile[r * 65 + g * 8 + j]));
        uint4 uh;
        uh.x = h[0] | (h[1] << 16); uh.y = h[2] | (h[3] << 16);
        uh.z = h[4] | (h[5] << 16); uh.w = h[6] | (h[7] << 16);
        const size_t off = (size_t)(R0 + r) * CC + C0 + g * 8;
        *(uint4*)(g_xhi + off) = uh;
    }

    const int bb = R0 >> 12;
    const int n0 = R0 & 4095;
    #pragma unroll
    for (int t = 0; t < 2; ++t) {
        const int id = tid + t * 256;
        const int c = id >> 3, g = id & 7;
        ushort h[8], l[8];
        #pragma unroll
        for (int j = 0; j < 8; j++) {
            __half hb, lb; split1(tile[(g * 8 + j) * 65 + c], hb, lb);
            h[j] = hfu(hb); l[j] = hfu(lb);
        }
        uint4 uh, ul;
        uh.x = h[0] | (h[1] << 16); uh.y = h[2] | (h[3] << 16);
        uh.z = h[4] | (h[5] << 16); uh.w = h[6] | (h[7] << 16);
        ul.x = l[0] | (l[1] << 16); ul.y = l[2] | (l[3] << 16);
        ul.z = l[4] | (l[5] << 16); ul.w = l[6] | (l[7] << 16);
        const size_t off = ((size_t)bb * CC + C0 + c) * NT + n0 + g * 8;
        *(uint4*)(g_xThi + off) = uh;
        *(uint4*)(g_xTlo + off) = ul;
    }
}

// ---------------------------------------------------------------------------
// prep: blocks [0,576) wq hi/lo split; [576,1152) wp hi split;
//       blocks [1152,1168) colsum reduction.
// ---------------------------------------------------------------------------
__global__ __launch_bounds__(256)
void prep_kernel(const float4* __restrict__ wq, const float4* __restrict__ wp)
{
    const int blk = blockIdx.x;
    const int tid = threadIdx.x;
    if (blk < 576) {
        const int j = blk * 256 + tid;
        float4 v = wq[j];
        float a[4] = {v.x, v.y, v.z, v.w};
        ushort h[4], l[4];
        #pragma unroll
        for (int t = 0; t < 4; t++) {
            __half hb, lb; split1(a[t], hb, lb);
            h[t] = hfu(hb); l[t] = hfu(lb);
        }
        ((ushort4*)g_wqh)[j] = make_ushort4(h[0], h[1], h[2], h[3]);
        ((ushort4*)g_wql)[j] = make_ushort4(l[0], l[1], l[2], l[3]);
    } else if (blk < 1152) {
        const int j = (blk - 576) * 256 + tid;
        float4 v = wp[j];
        ushort h[4];
        h[0] = hfu(__float2half_rn(v.x));
        h[1] = hfu(__float2half_rn(v.y));
        h[2] = hfu(__float2half_rn(v.z));
        h[3] = hfu(__float2half_rn(v.w));
        ((ushort4*)g_wph)[j] = make_ushort4(h[0], h[1], h[2], h[3]);
    } else {
        const int b = blk - 1152;
        #pragma unroll
        for (int p = 0; p < 3; ++p) {
            const int c = p * 256 + tid;
            float s = 0.f;
            for (int k = 0; k < 64; ++k)
                s += g_part2[(size_t)(b * 64 + k) * CC + c];
            g_s[b * CC + c] = s;
        }
    }
}

// ---------------------------------------------------------------------------
// U[b][row] = dot(w_qkv[row], s_b), rows 0..1535
// ---------------------------------------------------------------------------
__global__ __launch_bounds__(256)
void uw_kernel(const float* __restrict__ w_qkv)
{
    __shared__ float ss[CC];
    const int b = blockIdx.y, tid = threadIdx.x;
    #pragma unroll
    for (int p = 0; p < 3; ++p) ss[p * 256 + tid] = g_s[b * CC + p * 256 + tid];
    __syncthreads();
    const int row = blockIdx.x * 8 + (tid >> 5);
    const int lane = tid & 31;
    const float* wr = w_qkv + (size_t)row * CC;
    float acc = 0.f;
    #pragma unroll
    for (int k = 0; k < 24; ++k) acc += wr[lane + k * 32] * ss[lane + k * 32];
    #pragma unroll
    for (int off = 16; off > 0; off >>= 1)
        acc += __shfl_xor_sync(0xffffffffu, acc, off);
    if (lane == 0) g_U[b * 1536 + row] = acc;
}

// ---------------------------------------------------------------------------
// biasf[b][j] = b_proj[j] + dot(w_proj[j], r_b)
// ---------------------------------------------------------------------------
__global__ __launch_bounds__(256)
void biasf_kernel(const float* __restrict__ w_proj, const float* __restrict__ b_proj)
{
    __shared__ float rr[CC];
    const int b = blockIdx.y, tid = threadIdx.x;
    #pragma unroll
    for (int p = 0; p < 3; ++p) rr[p * 256 + tid] = g_r[b * CC + p * 256 + tid];
    __syncthreads();
    const int j = blockIdx.x * 8 + (tid >> 5);
    const int lane = tid & 31;
    const float* wr = w_proj + (size_t)j * CC;
    float acc = 0.f;
    #pragma unroll
    for (int k = 0; k < 24; ++k) acc += wr[lane + k * 32] * rr[lane + k * 32];
    #pragma unroll
    for (int off = 16; off > 0; off >>= 1)
        acc += __shfl_xor_sync(0xffffffffu, acc, off);
    if (lane == 0) g_biasf[b * CC + j] = b_proj[j] + acc;
}

#define SROW 80
#define TILE_B (128 * SROW)
#define SMEM_01 (2 * 4 * TILE_B)    // 81920 (modes 0,1)
#define SMEM_23 (5 * 2 * TILE_B)    // 102400 (modes 2,3)

// ---------------------------------------------------------------------------
// tgemm_wide: modes 0/1, 3-pass, 128 threads, 4 warps (2m x 2n),
// warp tile 64x64 (halves LDSM re-reads vs 64x32). Numerics identical to R12.
//   MODE 0: G partials (K-split, fp32 out), grid (21, KSPL, BB); diag dedup
//   MODE 1: T_b = Wq @ G_b (K=768, fp32 out), grid (6, 6, BB)
// ---------------------------------------------------------------------------
template <int MODE>
__global__ __launch_bounds__(128, 2)
void tgemm_wide(float* __restrict__ Cp)
{
    constexpr int NSTAGE = 2;
    constexpr int STAGE_B = 4 * TILE_B;

    int bm = blockIdx.y, bn = blockIdx.x;
    int b = blockIdx.z;
    int ksplit = 0;
    if (MODE == 0) {
        int t = blockIdx.x;
        bm = 0;
        while (t >= 6 - bm) { t -= 6 - bm; bm++; }
        bn = bm + t;
        ksplit = blockIdx.y;
    }
    const bool diag = (MODE == 0) && (bm == bn);

    const __half *Ah, *Al, *Wh, *Wl;
    constexpr int KROW  = (MODE == 0) ? 4096 : 768;
    constexpr int KITER = (MODE == 0) ? 1024 : 768;

    if (MODE == 0) {
        const size_t ab = ((size_t)b * CC + bm * 128) * NT + ksplit * KITER;
        const size_t wb = ((size_t)b * CC + bn * 128) * NT + ksplit * KITER;
        Ah = g_xThi + ab; Al = g_xTlo + ab;
        Wh = g_xThi + wb; Wl = g_xTlo + wb;
    } else {
        Ah = g_wqh + (size_t)bm * 128 * CC; Al = g_wql + (size_t)bm * 128 * CC;
        const size_t wb = (size_t)b * GSZ + (size_t)bn * 128 * CC;
        Wh = g_Ghi + wb; Wl = g_Glo + wb;
    }

    extern __shared__ char smem[];
    const uint32_t ubase = smem_u32(smem);

    const int tid  = threadIdx.x;           // 0..127
    const int wid  = tid >> 5;               // 0..3
    const int lane = tid & 31;
    const int wm   = wid & 1;                // 2 m-warps (64 rows each)
    const int wn   = wid >> 1;               // 2 n-warps (64 cols each)

    const int cr = tid >> 2;                 // 0..31
    const int cg = tid & 3;                  // 0..3

    const uint32_t boff = diag ? 0u : 2u * TILE_B;

    #define ISSUEW(s) do { \
        const uint32_t sb_ = ubase + ((s) & 1) * STAGE_B; \
        const int kof_ = (s) * 32; \
        _Pragma("unroll") \
        for (int t_ = 0; t_ < 4; ++t_) { \
            const int r_ = cr + t_ * 32; \
            const size_t off_ = (size_t)r_ * KROW + kof_ + cg * 8; \
            const uint32_t d_ = sb_ + r_ * SROW + cg * 16; \
            cp16(d_ + 0 * TILE_B, Ah + off_); \
            cp16(d_ + 1 * TILE_B, Al + off_); \
            if (!diag) { \
                cp16(d_ + 2 * TILE_B, Wh + off_); \
                cp16(d_ + 3 * TILE_B, Wl + off_); \
            } \
        } \
        cp_commit(); \
    } while (0)

    float acc[4][8][4];
    #pragma unroll
    for (int i = 0; i < 4; i++)
        #pragma unroll
        for (int j = 0; j < 8; j++)
            #pragma unroll
            for (int q = 0; q < 4; q++) acc[i][j][q] = 0.f;

    const int laneRA = lane & 15;
    const int laneGA = lane >> 4;
    const int laneRB = (lane & 7) | ((lane >> 4) << 3);
    const int laneGB = (lane >> 3) & 1;

    const int NK = KITER >> 5;

    ISSUEW(0);
    ISSUEW(1);

    for (int kb = 0; kb < NK; ++kb) {
        if (kb + 1 < NK) cp_wait<1>(); else cp_wait<0>();
        __syncthreads();

        const uint32_t sb = ubase + (kb & 1) * STAGE_B;
        const uint32_t aBase = sb + (wm * 64 + laneRA) * SROW + laneGA * 16;
        const uint32_t bBase = sb + boff + (wn * 64 + laneRB) * SROW + laneGB * 16;

        #pragma unroll
        for (int ks = 0; ks < 2; ++ks) {
            const uint32_t ko = ks * 32;
            uint32_t bh[8][2], bl[8][2];
            #pragma unroll
            for (int fp = 0; fp < 4; fp++) {
                uint32_t q[4];
                ldsm_x4(q, bBase + fp * (16 * SROW) + ko);
                bh[2 * fp][0] = q[0]; bh[2 * fp][1] = q[1];
                bh[2 * fp + 1][0] = q[2]; bh[2 * fp + 1][1] = q[3];
                ldsm_x4(q, bBase + TILE_B + fp * (16 * SROW) + ko);
                bl[2 * fp][0] = q[0]; bl[2 * fp][1] = q[1];
                bl[2 * fp + 1][0] = q[2]; bl[2 * fp + 1][1] = q[3];
            }
            #pragma unroll
            for (int fm = 0; fm < 4; fm++) {
                uint32_t ah[4], al[4];
                ldsm_x4(ah, aBase + fm * (16 * SROW) + ko);
                ldsm_x4(al, aBase + TILE_B + fm * (16 * SROW) + ko);
                #pragma unroll
                for (int fn = 0; fn < 8; fn++) {
                    mma16816(acc[fm][fn], ah, bh[fn]);
                    mma16816(acc[fm][fn], ah, bl[fn]);
                    mma16816(acc[fm][fn], al, bh[fn]);
                }
            }
        }

        if (kb + 2 < NK) {
            __syncthreads();
            ISSUEW(kb + 2);
        }
    }

    const int gid4 = lane >> 2;
    const int tig  = lane & 3;

    if (MODE == 0) {
        float* P = g_Gpart + (((size_t)b * KSPL + ksplit) * 21 + blockIdx.x) * 16384;
        #pragma unroll
        for (int fm = 0; fm < 4; fm++) {
            const int m0 = wm * 64 + fm * 16 + gid4;
            #pragma unroll
            for (int fn = 0; fn < 8; fn++) {
                const int col = wn * 64 + fn * 8 + tig * 2;
                *(float2*)(P + (size_t)m0 * 128 + col) =
                    make_float2(acc[fm][fn][0], acc[fm][fn][1]);
                *(float2*)(P + (size_t)(m0 + 8) * 128 + col) =
                    make_float2(acc[fm][fn][2], acc[fm][fn][3]);
            }
        }
    } else {
        float* C = g_T + (size_t)b * GSZ;
        #pragma unroll
        for (int fm = 0; fm < 4; fm++) {
            const int m0 = bm * 128 + wm * 64 + fm * 16 + gid4;
            #pragma unroll
            for (int fn = 0; fn < 8; fn++) {
                const int col = bn * 128 + wn * 64 + fn * 8 + tig * 2;
                *(float2*)(C + (size_t)m0 * CC + col) =
                    make_float2(acc[fm][fn][0], acc[fm][fn][1]);
                *(float2*)(C + (size_t)(m0 + 8) * CC + col) =
                    make_float2(acc[fm][fn][2], acc[fm][fn][3]);
            }
        }
    }
    #undef ISSUEW
}

// ---------------------------------------------------------------------------
// tgemm_kernel: single-pass modes (unchanged from R12).
//   MODE 2: P_b = Wp_hi @ MT_hi  (fp16 hi out)
//   MODE 3: out = X_hi @ P_hi^T + biasf
// 2 tiles/stage, 5-stage, single barrier per chunk.
// ---------------------------------------------------------------------------
template <int MODE>
__global__ __launch_bounds__(256, 2)
void tgemm_kernel(float* __restrict__ Cp)
{
    constexpr int NSTAGE = 5;
    constexpr int STAGE_B = 2 * TILE_B;

    int bm = blockIdx.y, bn = blockIdx.x;
    int b = blockIdx.z;

    const __half *Ah, *Wh;
    constexpr int KROW = 768;
    constexpr int KITER = 768;

    if (MODE == 2) {
        Ah = g_wph + (size_t)bm * 128 * CC;
        Wh = g_MThi + (size_t)b * GSZ + (size_t)bn * 128 * CC;
    } else {
        b = bm >> 5;
        Ah = g_xhi + (size_t)bm * 128 * CC;
        Wh = g_Phi + (size_t)b * GSZ + (size_t)bn * 128 * CC;
    }

    extern __shared__ char smem[];
    const uint32_t ubase = smem_u32(smem);

    const int tid  = threadIdx.x;
    const int wid  = tid >> 5;
    const int lane = tid & 31;
    const int wm   = wid & 1;
    const int wn   = wid >> 1;

    const int cr = tid >> 2;
    const int cg = tid & 3;

    #define ISSUE(s) do { \
        const uint32_t sb_ = ubase + ((s) % NSTAGE) * STAGE_B; \
        const int kof_ = (s) * 32; \
        _Pragma("unroll") \
        for (int t_ = 0; t_ < 2; ++t_) { \
            const int r_ = cr + t_ * 64; \
            const size_t off_ = (size_t)r_ * KROW + kof_ + cg * 8; \
            const uint32_t d_ = sb_ + r_ * SROW + cg * 16; \
            cp16(d_, Ah + off_); \
            cp16(d_ + TILE_B, Wh + off_); \
        } \
        cp_commit(); \
    } while (0)

    float acc[4][4][4];
    #pragma unroll
    for (int i = 0; i < 4; i++)
        #pragma unroll
        for (int j = 0; j < 4; j++)
            #pragma unroll
            for (int q = 0; q < 4; q++) acc[i][j][q] = 0.f;

    const int laneRA = lane & 15;
    const int laneGA = lane >> 4;
    const int laneRB = (lane & 7) | ((lane >> 4) << 3);
    const int laneGB = (lane >> 3) & 1;

    const int NK = KITER >> 5;

    ISSUE(0); ISSUE(1); ISSUE(2); ISSUE(3);

    for (int kb = 0; kb < NK; ++kb) {
        if (kb + 4 <= NK) cp_wait<3>();
        else if (kb + 3 <= NK) cp_wait<2>();
        else if (kb + 2 <= NK) cp_wait<1>();
        else cp_wait<0>();
        __syncthreads();
        if (kb + 4 < NK) ISSUE(kb + 4);

        const uint32_t sb = ubase + (kb % NSTAGE) * STAGE_B;
        const uint32_t aBase = sb + (wm * 64 + laneRA) * SROW + laneGA * 16;
        const uint32_t bBase = sb + TILE_B + (wn * 32 + laneRB) * SROW + laneGB * 16;

        #pragma unroll
        for (int ks = 0; ks < 2; ++ks) {
            const uint32_t ko = ks * 32;
            uint32_t bh[4][2];
            #pragma unroll
            for (int fp = 0; fp < 2; fp++) {
                uint32_t q[4];
                ldsm_x4(q, bBase + fp * (16 * SROW) + ko);
                bh[2 * fp][0] = q[0]; bh[2 * fp][1] = q[1];
                bh[2 * fp + 1][0] = q[2]; bh[2 * fp + 1][1] = q[3];
            }
            #pragma unroll
            for (int fm = 0; fm < 4; fm++) {
                uint32_t ah[4];
                ldsm_x4(ah, aBase + fm * (16 * SROW) + ko);
                #pragma unroll
                for (int fn = 0; fn < 4; fn++)
                    mma16816(acc[fm][fn], ah, bh[fn]);
            }
        }
    }

    const int gid4 = lane >> 2;
    const int tig  = lane & 3;

    if (MODE == 3) {
        float* C = Cp;
        const float* bias = g_biasf + b * CC;
        #pragma unroll
        for (int fm = 0; fm < 4; fm++) {
            const int m0 = bm * 128 + wm * 64 + fm * 16 + gid4;
            #pragma unroll
            for (int fn = 0; fn < 4; fn++) {
                const int col = bn * 128 + wn * 32 + fn * 8 + tig * 2;
                const float bx = bias[col], by = bias[col + 1];
                float2 o;
                o.x = acc[fm][fn][0] + bx; o.y = acc[fm][fn][1] + by;
                *(float2*)(C + (size_t)m0 * CC + col) = o;
                o.x = acc[fm][fn][2] + bx; o.y = acc[fm][fn][3] + by;
                *(float2*)(C + (size_t)(m0 + 8) * CC + col) = o;
            }
        }
    } else {   // MODE 2: P hi only
        __half* Hi = g_Phi + (size_t)b * GSZ;
        #pragma unroll
        for (int fm = 0; fm < 4; fm++) {
            const int m0 = bm * 128 + wm * 64 + fm * 16 + gid4;
            #pragma unroll
            for (int fn = 0; fn < 4; fn++) {
                const int col = bn * 128 + wn * 32 + fn * 8 + tig * 2;
                *(ushort2*)(Hi + (size_t)m0 * CC + col) =
                    make_ushort2(hfu(__float2half_rn(acc[fm][fn][0])),
                                 hfu(__float2half_rn(acc[fm][fn][1])));
                *(ushort2*)(Hi + (size_t)(m0 + 8) * CC + col) =
                    make_ushort2(hfu(__float2half_rn(acc[fm][fn][2])),
                                 hfu(__float2half_rn(acc[fm][fn][3])));
            }
        }
    }
    #undef ISSUE
}

// ---------------------------------------------------------------------------
// greduce: sum KSPL partials of one 64-row half of a G tile, split to fp16
// hi/lo, write tile + symmetric mirror. grid (21, 16, 2), block 256.
// ---------------------------------------------------------------------------
__global__ __launch_bounds__(256)
void greduce_kernel()
{
    __shared__ float s[64][132];
    int t = blockIdx.x;
    const int b = blockIdx.y;
    const int hhalf = blockIdx.z;
    int bm = 0;
    while (t >= 6 - bm) { t -= 6 - bm; bm++; }
    const int bn = bm + t;
    const int tid = threadIdx.x;

    const float* P0 = g_Gpart + (((size_t)b * KSPL) * 21 + blockIdx.x) * 16384;
    const float* P1 = P0 + (size_t)21 * 16384;
    const float* P2 = P1 + (size_t)21 * 16384;
    const float* P3 = P2 + (size_t)21 * 16384;
    __half* Hi = g_Ghi + (size_t)b * GSZ;
    __half* Lo = g_Glo + (size_t)b * GSZ;

    const int rbase = hhalf * 64;
    for (int e4 = tid; e4 < 2048; e4 += 256) {
        const int r = e4 >> 5, c4 = e4 & 31;
        const size_t o = (size_t)(rbase + r) * 128 + c4 * 4;
        float4 a = *(const float4*)(P0 + o);
        float4 bb = *(const float4*)(P1 + o);
        float4 c = *(const float4*)(P2 + o);
        float4 d = *(const float4*)(P3 + o);
        s[r][c4 * 4 + 0] = a.x + bb.x + c.x + d.x;
        s[r][c4 * 4 + 1] = a.y + bb.y + c.y + d.y;
        s[r][c4 * 4 + 2] = a.z + bb.z + c.z + d.z;
        s[r][c4 * 4 + 3] = a.w + bb.w + c.w + d.w;
    }
    __syncthreads();

    {
        const int r = tid >> 2, cb = (tid & 3) * 32;
        const size_t rowo = (size_t)(bm * 128 + rbase + r) * CC + bn * 128 + cb;
        #pragma unroll
        for (int k = 0; k < 32; k += 8) {
            ushort hh[8], ll[8];
            #pragma unroll
            for (int j = 0; j < 8; ++j) {
                __half hb, lb; split1(s[r][cb + k + j], hb, lb);
                hh[j] = hfu(hb); ll[j] = hfu(lb);
            }
            uint4 uh, ul;
            uh.x = hh[0] | (hh[1] << 16); uh.y = hh[2] | (hh[3] << 16);
            uh.z = hh[4] | (hh[5] << 16); uh.w = hh[6] | (hh[7] << 16);
            ul.x = ll[0] | (ll[1] << 16); ul.y = ll[2] | (ll[3] << 16);
            ul.z = ll[4] | (ll[5] << 16); ul.w = ll[6] | (ll[7] << 16);
            *(uint4*)(Hi + rowo + k) = uh;
            *(uint4*)(Lo + rowo + k) = ul;
        }
    }
    if (bm != bn) {
        const int j = tid >> 1, cb = (tid & 1) * 32;
        const size_t rowo = (size_t)(bn * 128 + j) * CC + bm * 128 + rbase + cb;
        #pragma unroll
        for (int k = 0; k < 32; k += 8) {
            ushort hh[8], ll[8];
            #pragma unroll
            for (int jj = 0; jj < 8; ++jj) {
                __half hb, lb; split1(s[cb + k + jj][j], hb, lb);
                hh[jj] = hfu(hb); ll[jj] = hfu(lb);
            }
            uint4 uh, ul;
            uh.x = hh[0] | (hh[1] << 16); uh.y = hh[2] | (hh[3] << 16);
            uh.z = hh[4] | (hh[5] << 16); uh.w = hh[6] | (hh[7] << 16);
            ul.x = ll[0] | (ll[1] << 16); ul.y = ll[2] | (ll[3] << 16);
            ul.z = ll[4] | (ll[5] << 16); ul.w = ll[6] | (ll[7] << 16);
            *(uint4*)(Hi + rowo + k) = uh;
            *(uint4*)(Lo + rowo + k) = ul;
        }
    }
}

// ---------------------------------------------------------------------------
// logits + softmax per (b,h), 2 d-halves. grid (128, 2).
// ---------------------------------------------------------------------------
#define WOFF 1600
__global__ __launch_bounds__(256)
void logits_kernel(const float* __restrict__ w_qkv, const float* __restrict__ b_qkv)
{
    const int bh = blockIdx.x;
    const int yh = blockIdx.y;
    const int b = bh >> 3, h = bh & 7;

    __shared__ float buf[WOFF + 3104];
    __shared__ float bqs[48], ws_[48], bks[96], us_[96];

    const int tid = threadIdx.x;
    const int tx = tid & 15;
    const int ty = tid >> 4;

    if (tid < 48) {
        bqs[tid] = b_qkv[h * DD + yh * 48 + tid];
        ws_[tid] = g_U[b * 1536 + h * DD + yh * 48 + tid];
    }
    if (tid < 96) {
        bks[tid] = b_qkv[CC + h * DD + tid];
        us_[tid] = g_U[b * 1536 + CC + h * DD + tid];
    }

    const float* Tb = g_T + (size_t)b * GSZ + (size_t)(h * DD + yh * 48) * CC;
    const float* Wk = w_qkv + (size_t)(CC + h * DD) * CC;

    float acc[3][6];
    #pragma unroll
    for (int i = 0; i < 3; i++)
        #pragma unroll
        for (int j = 0; j < 6; j++) acc[i][j] = 0.f;

    for (int c0 = 0; c0 < CC; c0 += 32) {
        __syncthreads();
        for (int id = tid; id < 384 + 768; id += 256) {
            if (id < 384) {
                const int row = id >> 3, f4 = id & 7;
                float4 tv = *(const float4*)(Tb + (size_t)row * CC + c0 + f4 * 4);
                buf[(f4 * 4 + 0) * 49 + row] = tv.x;
                buf[(f4 * 4 + 1) * 49 + row] = tv.y;
                buf[(f4 * 4 + 2) * 49 + row] = tv.z;
                buf[(f4 * 4 + 3) * 49 + row] = tv.w;
            } else {
                const int id2 = id - 384;
                const int row = id2 >> 3, f4 = id2 & 7;
                float4 kv = *(const float4*)(Wk + (size_t)row * CC + c0 + f4 * 4);
                buf[WOFF + (f4 * 4 + 0) * 97 + row] = kv.x;
                buf[WOFF + (f4 * 4 + 1) * 97 + row] = kv.y;
                buf[WOFF + (f4 * 4 + 2) * 97 + row] = kv.z;
                buf[WOFF + (f4 * 4 + 3) * 97 + row] = kv.w;
            }
        }
        __syncthreads();
        #pragma unroll 8
        for (int kk = 0; kk < 32; ++kk) {
            float qr[3], kr[6];
            #pragma unroll
            for (int i = 0; i < 3; i++)
                qr[i] = buf[kk * 49 + ty * 3 + i];
            #pragma unroll
            for (int j = 0; j < 6; j++)
                kr[j] = buf[WOFF + kk * 97 + tx * 6 + j];
            #pragma unroll
            for (int i = 0; i < 3; i++)
                #pragma unroll
                for (int j = 0; j < 6; j++)
                    acc[i][j] = fmaf(qr[i], kr[j], acc[i][j]);
        }
    }
    __syncthreads();

    const float scale = 0.015625f;
    #pragma unroll
    for (int i = 0; i < 3; i++) {
        const int dl = ty * 3 + i;
        #pragma unroll
        for (int j = 0; j < 6; j++) {
            const int e = tx * 6 + j;
            float v = acc[i][j] + bqs[dl] * us_[e] + bks[e] * ws_[dl]
                      + 4096.f * bqs[dl] * bks[e];
            buf[dl * 96 + e] = v * scale;
        }
    }
    __syncthreads();

    const int wid = tid >> 5, lane = tid & 31;
    for (int r = wid; r < 48; r += 8) {
        float v0 = buf[r * 96 + lane];
        float v1 = buf[r * 96 + 32 + lane];
        float v2 = buf[r * 96 + 64 + lane];
        float m = fmaxf(v0, fmaxf(v1, v2));
        #pragma unroll
        for (int off = 16; off > 0; off >>= 1)
            m = fmaxf(m, __shfl_xor_sync(0xffffffffu, m, off));
        float e0 = expf(v0 - m), e1 = expf(v1 - m), e2 = expf(v2 - m);
        float s = e0 + e1 + e2;
        #pragma unroll
        for (int off = 16; off > 0; off >>= 1)
            s += __shfl_xor_sync(0xffffffffu, s, off);
        const float inv = 1.f / s;
        float* arow = g_attn + ((size_t)bh * 96 + yh * 48 + r) * 96;
        arow[lane]      = e0 * inv;
        arow[lane + 32] = e1 * inv;
        arow[lane + 64] = e2 * inv;
    }
}

// ---------------------------------------------------------------------------
// MT_b[c, h*96+d] = sum_e A_bh[d,e] Wv[h*96+e, c]  (fp16 hi only); grid (6,128)
// ---------------------------------------------------------------------------
__global__ __launch_bounds__(256)
void mt_kernel(const float* __restrict__ w_qkv, const float* __restrict__ b_qkv)
{
    const int c0 = blockIdx.x * 128;
    const int bh = blockIdx.y;
    const int b = bh >> 3, h = bh & 7;

    __shared__ float As[96 * 97];
    __shared__ float Ws[16 * 132];
    __shared__ float bvs[96];

    const int tid = threadIdx.x;
    const int tx = tid & 15;
    const int ty = tid >> 4;

    const float* asrc = g_attn + (size_t)bh * 9216;
    for (int id = tid; id < 9216; id += 256) {
        const int r = id / 96, c = id - r * 96;
        As[r * 97 + c] = asrc[id];
    }
    if (tid < 96) bvs[tid] = b_qkv[2 * CC + h * DD + tid];
    __syncthreads();

    if (blockIdx.x == 0 && tid < 96) {
        float rv = 0.f;
        #pragma unroll 4
        for (int e = 0; e < 96; ++e) rv += As[tid * 97 + e] * bvs[e];
        g_r[b * CC + h * DD + tid] = rv;
    }

    const float* Wv = w_qkv + (size_t)(2 * CC + h * DD) * CC;
    __half* MTh = g_MThi + (size_t)b * GSZ;

    float acc[8][6];
    #pragma unroll
    for (int i = 0; i < 8; i++)
        #pragma unroll
        for (int j = 0; j < 6; j++) acc[i][j] = 0.f;

    for (int e0 = 0; e0 < 96; e0 += 16) {
        if (e0) __syncthreads();
        #pragma unroll
        for (int t = 0; t < 2; ++t) {
            const int id = tid + t * 256;
            const int e = id >> 5, f4 = id & 31;
            float4 v = *(const float4*)(Wv + (size_t)(e0 + e) * CC + c0 + f4 * 4);
            *(float4*)&Ws[e * 132 + f4 * 4] = v;
        }
        __syncthreads();
        #pragma unroll
        for (int e = 0; e < 16; ++e) {
            float vv[8], aa[6];
            #pragma unroll
            for (int i = 0; i < 8; i++) vv[i] = Ws[e * 132 + ty * 8 + i];
            #pragma unroll
            for (int j = 0; j < 6; j++) aa[j] = As[(tx * 6 + j) * 97 + e0 + e];
            #pragma unroll
            for (int i = 0; i < 8; i++)
                #pragma unroll
                for (int j = 0; j < 6; j++)
                    acc[i][j] = fmaf(vv[i], aa[j], acc[i][j]);
        }
    }
    #pragma unroll
    for (int i = 0; i < 8; i++) {
        const int c = c0 + ty * 8 + i;
        const size_t base = (size_t)c * CC + h * DD + tx * 6;
        #pragma unroll
        for (int j = 0; j < 6; j += 2) {
            *(ushort2*)(MTh + base + j) =
                make_ushort2(hfu(__float2half_rn(acc[i][j])),
                             hfu(__float2half_rn(acc[i][j + 1])));
        }
    }
}

// ---------------------------------------------------------------------------
extern "C" void kernel_launch(void* const* d_in, const int* in_sizes, int n_in,
                              void* d_out, int out_size)
{
    const float* x      = (const float*)d_in[0];
    const float* w_qkv  = (const float*)d_in[1];
    const float* b_qkv  = (const float*)d_in[2];
    const float* w_proj = (const float*)d_in[3];
    const float* b_proj = (const float*)d_in[4];
    float*       out    = (float*)d_out;

    cudaFuncSetAttribute(tgemm_wide<0>,
                         cudaFuncAttributeMaxDynamicSharedMemorySize, SMEM_01);
    cudaFuncSetAttribute(tgemm_wide<1>,
                         cudaFuncAttributeMaxDynamicSharedMemorySize, SMEM_01);
    cudaFuncSetAttribute(tgemm_kernel<2>,
                         cudaFuncAttributeMaxDynamicSharedMemorySize, SMEM_23);
    cudaFuncSetAttribute(tgemm_kernel<3>,
                         cudaFuncAttributeMaxDynamicSharedMemorySize, SMEM_23);

    // 0) splits + transposed splits + fused column sums; weight splits + colsum
    transpose_split_kernel<<<dim3(12, 1024), 256>>>(x);
    prep_kernel<<<1168, 256>>>((const float4*)w_qkv, (const float4*)w_proj);

    // 1) G partials (3-pass, K-split x4, diag dedup, warp 64x64)
    tgemm_wide<0><<<dim3(21, KSPL, BB), 128, SMEM_01>>>(nullptr);
    greduce_kernel<<<dim3(21, BB, 2), 256>>>();

    // 2) T_b = Wq @ G_b  (3-pass, warp 64x64)
    tgemm_wide<1><<<dim3(6, 6, BB), 128, SMEM_01>>>(nullptr);

    // 3) rank-1 correction dots, logits + softmax (d-split x2)
    uw_kernel<<<dim3(192, BB), 256>>>(w_qkv);
    logits_kernel<<<dim3(BB * HH, 2), 256>>>(w_qkv, b_qkv);

    // 4) MT_b = (A @ Wv)^T stacked (fp16 hi only); r_bh
    mt_kernel<<<dim3(6, BB * HH), 256>>>(w_qkv, b_qkv);

    // 5) P_b = Wp_hi @ MT_hi (single-pass, 5-stage); fused output bias
    biasf_kernel<<<dim3(96, BB), 256>>>(w_proj, b_proj);
    tgemm_kernel<2><<<dim3(6, 6, BB), 256, SMEM_23>>>(nullptr);

    // 6) out = Xhi @ Phi^T + biasf   (single-pass fp16, 5-stage)
    tgemm_kernel<3><<<dim3(6, 512, 1), 256, SMEM_23>>>(out);
}

// round 14
// speedup vs baseline: 1.1278x; 1.1278x over previous
#include <cuda_runtime.h>
#include <cuda_fp16.h>
#include <cstdint>

// Problem constants
#define BB   16
#define NT   4096
#define CC   768
#define HH   8
#define DD   96
#define MM   (BB * NT)          // 65536
#define GSZ  (768 * 768)        // 589824
#define KSPL 4                  // K-split for the G GEMM

// ---------------------------------------------------------------------------
// Scratch (__device__ globals)
// ---------------------------------------------------------------------------
__device__ __half g_xhi[(size_t)MM * CC];
__device__ __half g_xThi[(size_t)MM * CC], g_xTlo[(size_t)MM * CC]; // [b,c,n]
__device__ float g_Gpart[(size_t)BB * KSPL * 21 * 16384];           // fp32 partials
__device__ __half g_Ghi[BB * GSZ], g_Glo[BB * GSZ];
__device__ float g_T[BB * GSZ];
__device__ float g_attn[BB * HH * DD * DD];
__device__ __half g_MThi[BB * GSZ];                     // [b, c, h*96+d]
__device__ __half g_Phi[BB * GSZ];
__device__ __half g_wqh[GSZ], g_wql[GSZ];
__device__ __half g_wph[GSZ];
__device__ float g_s[BB * CC];
__device__ float g_part2[1024 * CC];                    // per-64-row-block colsums
__device__ float g_U[BB * 1536];
__device__ float g_r[BB * CC];
__device__ float g_biasf[BB * CC];

// ---------------------------------------------------------------------------
// PTX helpers (target-agnostic)
// ---------------------------------------------------------------------------
__device__ __forceinline__ uint32_t smem_u32(const void* p) {
    uint32_t a;
    asm("{ .reg .u64 t; cvta.to.shared.u64 t, %1; cvt.u32.u64 %0, t; }"
        : "=r"(a) : "l"(p));
    return a;
}
__device__ __forceinline__ void ldsm_x4(uint32_t* r, uint32_t addr) {
    asm volatile("ldmatrix.sync.aligned.m8n8.x4.shared.b16 {%0,%1,%2,%3}, [%4];"
                 : "=r"(r[0]), "=r"(r[1]), "=r"(r[2]), "=r"(r[3]) : "r"(addr));
}
__device__ __forceinline__ void mma16816(float* c, const uint32_t* a, const uint32_t* b) {
    asm volatile(
        "mma.sync.aligned.m16n8k16.row.col.f32.f16.f16.f32 "
        "{%0,%1,%2,%3}, {%4,%5,%6,%7}, {%8,%9}, {%0,%1,%2,%3};"
        : "+f"(c[0]), "+f"(c[1]), "+f"(c[2]), "+f"(c[3])
        : "r"(a[0]), "r"(a[1]), "r"(a[2]), "r"(a[3]), "r"(b[0]), "r"(b[1]));
}
__device__ __forceinline__ void cp16(uint32_t dst, const void* src) {
    asm volatile("cp.async.cg.shared.global [%0], [%1], 16;"
                 :: "r"(dst), "l"(src) : "memory");
}
__device__ __forceinline__ void cp_commit() {
    asm volatile("cp.async.commit_group;" ::: "memory");
}
template <int N>
__device__ __forceinline__ void cp_wait() {
    asm volatile("cp.async.wait_group %0;" :: "n"(N) : "memory");
}
__device__ __forceinline__ void split1(float v, __half& h, __half& l) {
    h = __float2half_rn(v);
    l = __float2half_rn(v - __half2float(h));
}
__device__ __forceinline__ ushort hfu(__half v) { return __half_as_ushort(v); }

// ---------------------------------------------------------------------------
// transpose_split: x -> row-major hi, per-batch transposed hi/lo,
// AND per-block column partial sums (fused colsum).
// ---------------------------------------------------------------------------
__global__ __launch_bounds__(256)
void transpose_split_kernel(const float* __restrict__ x)
{
    __shared__ float tile[64 * 65];
    __shared__ float colp[4][64];
    const int tid = threadIdx.x;
    const int C0 = blockIdx.x * 64;
    const int R0 = blockIdx.y * 64;

    #pragma unroll
    for (int t = 0; t < 4; ++t) {
        const int id = tid + t * 256;
        const int r = id >> 4, f4 = id & 15;
        float4 v = *(const float4*)(x + (size_t)(R0 + r) * CC + C0 + f4 * 4);
        tile[r * 65 + f4 * 4 + 0] = v.x;
        tile[r * 65 + f4 * 4 + 1] = v.y;
        tile[r * 65 + f4 * 4 + 2] = v.z;
        tile[r * 65 + f4 * 4 + 3] = v.w;
    }
    __syncthreads();

    {
        const int c = tid & 63, q = tid >> 6;
        float s = 0.f;
        #pragma unroll
        for (int r = 0; r < 16; ++r) s += tile[(q * 16 + r) * 65 + c];
        colp[q][c] = s;
    }
    __syncthreads();
    if (tid < 64)
        g_part2[(size_t)blockIdx.y * CC + C0 + tid] =
            colp[0][tid] + colp[1][tid] + colp[2][tid] + colp[3][tid];

    #pragma unroll
    for (int t = 0; t < 2; ++t) {
        const int id = tid + t * 256;
        const int r = id >> 3, g = id & 7;
        ushort h[8];
        #pragma unroll
        for (int j = 0; j < 8; j++)
            h[j] = hfu(__float2half_rn(tile[r * 65 + g * 8 + j]));
        uint4 uh;
        uh.x = h[0] | (h[1] << 16); uh.y = h[2] | (h[3] << 16);
        uh.z = h[4] | (h[5] << 16); uh.w = h[6] | (h[7] << 16);
        const size_t off = (size_t)(R0 + r) * CC + C0 + g * 8;
        *(uint4*)(g_xhi + off) = uh;
    }

    const int bb = R0 >> 12;
    const int n0 = R0 & 4095;
    #pragma unroll
    for (int t = 0; t < 2; ++t) {
        const int id = tid + t * 256;
        const int c = id >> 3, g = id & 7;
        ushort h[8], l[8];
        #pragma unroll
        for (int j = 0; j < 8; j++) {
            __half hb, lb; split1(tile[(g * 8 + j) * 65 + c], hb, lb);
            h[j] = hfu(hb); l[j] = hfu(lb);
        }
        uint4 uh, ul;
        uh.x = h[0] | (h[1] << 16); uh.y = h[2] | (h[3] << 16);
        uh.z = h[4] | (h[5] << 16); uh.w = h[6] | (h[7] << 16);
        ul.x = l[0] | (l[1] << 16); ul.y = l[2] | (l[3] << 16);
        ul.z = l[4] | (l[5] << 16); ul.w = l[6] | (l[7] << 16);
        const size_t off = ((size_t)bb * CC + C0 + c) * NT + n0 + g * 8;
        *(uint4*)(g_xThi + off) = uh;
        *(uint4*)(g_xTlo + off) = ul;
    }
}

// ---------------------------------------------------------------------------
// prep: blocks [0,576) wq hi/lo split; [576,1152) wp hi split;
//       blocks [1152,1168) colsum reduction.
// ---------------------------------------------------------------------------
__global__ __launch_bounds__(256)
void prep_kernel(const float4* __restrict__ wq, const float4* __restrict__ wp)
{
    const int blk = blockIdx.x;
    const int tid = threadIdx.x;
    if (blk < 576) {
        const int j = blk * 256 + tid;
        float4 v = wq[j];
        float a[4] = {v.x, v.y, v.z, v.w};
        ushort h[4], l[4];
        #pragma unroll
        for (int t = 0; t < 4; t++) {
            __half hb, lb; split1(a[t], hb, lb);
            h[t] = hfu(hb); l[t] = hfu(lb);
        }
        ((ushort4*)g_wqh)[j] = make_ushort4(h[0], h[1], h[2], h[3]);
        ((ushort4*)g_wql)[j] = make_ushort4(l[0], l[1], l[2], l[3]);
    } else if (blk < 1152) {
        const int j = (blk - 576) * 256 + tid;
        float4 v = wp[j];
        ushort h[4];
        h[0] = hfu(__float2half_rn(v.x));
        h[1] = hfu(__float2half_rn(v.y));
        h[2] = hfu(__float2half_rn(v.z));
        h[3] = hfu(__float2half_rn(v.w));
        ((ushort4*)g_wph)[j] = make_ushort4(h[0], h[1], h[2], h[3]);
    } else {
        const int b = blk - 1152;
        #pragma unroll
        for (int p = 0; p < 3; ++p) {
            const int c = p * 256 + tid;
            float s = 0.f;
            for (int k = 0; k < 64; ++k)
                s += g_part2[(size_t)(b * 64 + k) * CC + c];
            g_s[b * CC + c] = s;
        }
    }
}

// ---------------------------------------------------------------------------
// U[b][row] = dot(w_qkv[row], s_b), rows 0..1535
// ---------------------------------------------------------------------------
__global__ __launch_bounds__(256)
void uw_kernel(const float* __restrict__ w_qkv)
{
    __shared__ float ss[CC];
    const int b = blockIdx.y, tid = threadIdx.x;
    #pragma unroll
    for (int p = 0; p < 3; ++p) ss[p * 256 + tid] = g_s[b * CC + p * 256 + tid];
    __syncthreads();
    const int row = blockIdx.x * 8 + (tid >> 5);
    const int lane = tid & 31;
    const float* wr = w_qkv + (size_t)row * CC;
    float acc = 0.f;
    #pragma unroll
    for (int k = 0; k < 24; ++k) acc += wr[lane + k * 32] * ss[lane + k * 32];
    #pragma unroll
    for (int off = 16; off > 0; off >>= 1)
        acc += __shfl_xor_sync(0xffffffffu, acc, off);
    if (lane == 0) g_U[b * 1536 + row] = acc;
}

// ---------------------------------------------------------------------------
// biasf[b][j] = b_proj[j] + dot(w_proj[j], r_b)
// ---------------------------------------------------------------------------
__global__ __launch_bounds__(256)
void biasf_kernel(const float* __restrict__ w_proj, const float* __restrict__ b_proj)
{
    __shared__ float rr[CC];
    const int b = blockIdx.y, tid = threadIdx.x;
    #pragma unroll
    for (int p = 0; p < 3; ++p) rr[p * 256 + tid] = g_r[b * CC + p * 256 + tid];
    __syncthreads();
    const int j = blockIdx.x * 8 + (tid >> 5);
    const int lane = tid & 31;
    const float* wr = w_proj + (size_t)j * CC;
    float acc = 0.f;
    #pragma unroll
    for (int k = 0; k < 24; ++k) acc += wr[lane + k * 32] * rr[lane + k * 32];
    #pragma unroll
    for (int off = 16; off > 0; off >>= 1)
        acc += __shfl_xor_sync(0xffffffffu, acc, off);
    if (lane == 0) g_biasf[b * CC + j] = b_proj[j] + acc;
}

// ---------------------------------------------------------------------------
// HMMA fp16-split GEMM, templated on MODE. R12 structure, G now 2-pass.
//   MODE 0: Gpart = Xhi^T @ (Xhi + Xlo)  (2-PASS, K-split, fp32 out)
//           grid (21, KSPL, BB); diag: Bh deduped onto A slot, Bl in slot 1
//   MODE 1: T_b = Wq @ G_b       (K=768, 3-pass, fp32 out)
//   MODE 2: P_b = Wp_hi @ MT_hi  (K=768, 1-pass, fp16 hi out, 5-stage)
//   MODE 3: out = X_hi @ P_hi^T + biasf  (K=768, 1-pass, 5-stage)
// ---------------------------------------------------------------------------
#define SROW 80
#define TILE_B (128 * SROW)
#define SMEM_012 (2 * 4 * TILE_B)   // 81920 (modes 0,1)
#define SMEM_3   (5 * 2 * TILE_B)   // 102400 (modes 2,3)

template <int MODE>
__global__ __launch_bounds__(256, 2)
void tgemm_kernel(float* __restrict__ Cp)
{
    constexpr bool SINGLE = (MODE >= 2);
    constexpr int NTILES = SINGLE ? 2 : 4;
    constexpr int NSTAGE = SINGLE ? 5 : 2;
    constexpr int STAGE_B = NTILES * TILE_B;

    int bm = blockIdx.y, bn = blockIdx.x;
    int b = blockIdx.z;
    int ksplit = 0;
    if (MODE == 0) {
        int t = blockIdx.x;
        bm = 0;
        while (t >= 6 - bm) { t -= 6 - bm; bm++; }
        bn = bm + t;
        ksplit = blockIdx.y;
    }
    const bool diag = (MODE == 0) && (bm == bn);

    const __half *Ah, *Al = nullptr, *Wh, *Wl = nullptr;
    constexpr int KROW  = (MODE == 0) ? 4096 : 768;
    constexpr int KITER = (MODE == 0) ? 1024 : 768;

    if (MODE == 0) {
        const size_t ab = ((size_t)b * CC + bm * 128) * NT + ksplit * KITER;
        const size_t wb = ((size_t)b * CC + bn * 128) * NT + ksplit * KITER;
        Ah = g_xThi + ab;                    // A = Xhi(bm) only (2-pass)
        Wh = g_xThi + wb; Wl = g_xTlo + wb;  // B = Xhi(bn), Xlo(bn)
    } else if (MODE == 1) {
        Ah = g_wqh + (size_t)bm * 128 * CC; Al = g_wql + (size_t)bm * 128 * CC;
        const size_t wb = (size_t)b * GSZ + (size_t)bn * 128 * CC;
        Wh = g_Ghi + wb; Wl = g_Glo + wb;
    } else if (MODE == 2) {
        Ah = g_wph + (size_t)bm * 128 * CC;
        Wh = g_MThi + (size_t)b * GSZ + (size_t)bn * 128 * CC;
    } else {
        b = bm >> 5;
        Ah = g_xhi + (size_t)bm * 128 * CC;
        Wh = g_Phi + (size_t)b * GSZ + (size_t)bn * 128 * CC;
    }

    extern __shared__ char smem[];
    const uint32_t ubase = smem_u32(smem);

    const int tid  = threadIdx.x;
    const int wid  = tid >> 5;
    const int lane = tid & 31;
    const int wm   = wid & 1;
    const int wn   = wid >> 1;

    const int cr = tid >> 2;
    const int cg = tid & 3;

    // B operand smem base: modes 2/3 -> tile 1.
    // MODE 0: diag -> bh=tile0 (A alias), bl=tile1;  off-diag -> bh=2, bl=3.
    // MODE 1: bh=2, bl=3.
    const uint32_t boff = SINGLE ? TILE_B : (diag ? 0u : 2u * TILE_B);

    #define ISSUE(s) do { \
        const uint32_t sb_ = ubase + ((s) % NSTAGE) * STAGE_B; \
        const int kof_ = (s) * 32; \
        _Pragma("unroll") \
        for (int t_ = 0; t_ < 2; ++t_) { \
            const int r_ = cr + t_ * 64; \
            const size_t off_ = (size_t)r_ * KROW + kof_ + cg * 8; \
            const uint32_t d_ = sb_ + r_ * SROW + cg * 16; \
            cp16(d_ + 0 * TILE_B, Ah + off_); \
            if (SINGLE) { \
                cp16(d_ + TILE_B, Wh + off_); \
            } else if (MODE == 0) { \
                if (diag) { \
                    cp16(d_ + 1 * TILE_B, Wl + off_); \
                } else { \
                    cp16(d_ + 2 * TILE_B, Wh + off_); \
                    cp16(d_ + 3 * TILE_B, Wl + off_); \
                } \
            } else { \
                cp16(d_ + 1 * TILE_B, Al + off_); \
                cp16(d_ + 2 * TILE_B, Wh + off_); \
                cp16(d_ + 3 * TILE_B, Wl + off_); \
            } \
        } \
        cp_commit(); \
    } while (0)

    float acc[4][4][4];
    #pragma unroll
    for (int i = 0; i < 4; i++)
        #pragma unroll
        for (int j = 0; j < 4; j++)
            #pragma unroll
            for (int q = 0; q < 4; q++) acc[i][j][q] = 0.f;

    const int laneRA = lane & 15;
    const int laneGA = lane >> 4;
    const int laneRB = (lane & 7) | ((lane >> 4) << 3);
    const int laneGB = (lane >> 3) & 1;

    const int NK = KITER >> 5;

    if (SINGLE) { ISSUE(0); ISSUE(1); ISSUE(2); ISSUE(3); }
    else        { ISSUE(0); ISSUE(1); }

    for (int kb = 0; kb < NK; ++kb) {
        if (SINGLE) {
            if (kb + 4 <= NK) cp_wait<3>();
            else if (kb + 3 <= NK) cp_wait<2>();
            else if (kb + 2 <= NK) cp_wait<1>();
            else cp_wait<0>();
            __syncthreads();
            if (kb + 4 < NK) ISSUE(kb + 4);   // slot (kb-1)%5: readers done
        } else {
            if (kb + 1 < NK) cp_wait<1>(); else cp_wait<0>();
            __syncthreads();
        }

        const uint32_t sb = ubase + (kb % NSTAGE) * STAGE_B;
        const uint32_t aBase = sb + (wm * 64 + laneRA) * SROW + laneGA * 16;
        const uint32_t bBase = sb + boff + (wn * 32 + laneRB) * SROW + laneGB * 16;

        #pragma unroll
        for (int ks = 0; ks < 2; ++ks) {
            const uint32_t ko = ks * 32;
            uint32_t bh[4][2], bl[4][2];
            #pragma unroll
            for (int fp = 0; fp < 2; fp++) {
                uint32_t q[4];
                ldsm_x4(q, bBase + fp * (16 * SROW) + ko);
                bh[2 * fp][0] = q[0]; bh[2 * fp][1] = q[1];
                bh[2 * fp + 1][0] = q[2]; bh[2 * fp + 1][1] = q[3];
                if (!SINGLE) {
                    ldsm_x4(q, bBase + TILE_B + fp * (16 * SROW) + ko);
                    bl[2 * fp][0] = q[0]; bl[2 * fp][1] = q[1];
                    bl[2 * fp + 1][0] = q[2]; bl[2 * fp + 1][1] = q[3];
                }
            }
            #pragma unroll
            for (int fm = 0; fm < 4; fm++) {
                uint32_t ah[4], al[4];
                ldsm_x4(ah, aBase + fm * (16 * SROW) + ko);
                if (MODE == 1)
                    ldsm_x4(al, aBase + TILE_B + fm * (16 * SROW) + ko);
                #pragma unroll
                for (int fn = 0; fn < 4; fn++) {
                    mma16816(acc[fm][fn], ah, bh[fn]);
                    if (!SINGLE) mma16816(acc[fm][fn], ah, bl[fn]);
                    if (MODE == 1) mma16816(acc[fm][fn], al, bh[fn]);
                }
            }
        }

        if (!SINGLE && kb + 2 < NK) {
            __syncthreads();      // all warps done reading this buffer
            ISSUE(kb + 2);
        }
    }

    const int gid4 = lane >> 2;
    const int tig  = lane & 3;

    if (MODE == 1 || MODE == 3) {
        float* C = (MODE == 1) ? (g_T + (size_t)b * GSZ) : Cp;
        const float* bias = (MODE == 3) ? (g_biasf + b * CC) : nullptr;
        #pragma unroll
        for (int fm = 0; fm < 4; fm++) {
            const int m0 = bm * 128 + wm * 64 + fm * 16 + gid4;
            #pragma unroll
            for (int fn = 0; fn < 4; fn++) {
                const int col = bn * 128 + wn * 32 + fn * 8 + tig * 2;
                float bx = 0.f, by = 0.f;
                if (MODE == 3) { bx = bias[col]; by = bias[col + 1]; }
                float2 o;
                o.x = acc[fm][fn][0] + bx; o.y = acc[fm][fn][1] + by;
                *(float2*)(C + (size_t)m0 * CC + col) = o;
                o.x = acc[fm][fn][2] + bx; o.y = acc[fm][fn][3] + by;
                *(float2*)(C + (size_t)(m0 + 8) * CC + col) = o;
            }
        }
    } else if (MODE == 0) {
        float* P = g_Gpart + (((size_t)b * KSPL + ksplit) * 21 + blockIdx.x) * 16384;
        #pragma unroll
        for (int fm = 0; fm < 4; fm++) {
            const int m0 = wm * 64 + fm * 16 + gid4;
            #pragma unroll
            for (int fn = 0; fn < 4; fn++) {
                const int col = wn * 32 + fn * 8 + tig * 2;
                *(float2*)(P + (size_t)m0 * 128 + col) =
                    make_float2(acc[fm][fn][0], acc[fm][fn][1]);
                *(float2*)(P + (size_t)(m0 + 8) * 128 + col) =
                    make_float2(acc[fm][fn][2], acc[fm][fn][3]);
            }
        }
    } else {   // MODE 2: P hi only
        __half* Hi = g_Phi + (size_t)b * GSZ;
        #pragma unroll
        for (int fm = 0; fm < 4; fm++) {
            const int m0 = bm * 128 + wm * 64 + fm * 16 + gid4;
            #pragma unroll
            for (int fn = 0; fn < 4; fn++) {
                const int col = bn * 128 + wn * 32 + fn * 8 + tig * 2;
                *(ushort2*)(Hi + (size_t)m0 * CC + col) =
                    make_ushort2(hfu(__float2half_rn(acc[fm][fn][0])),
                                 hfu(__float2half_rn(acc[fm][fn][1])));
                *(ushort2*)(Hi + (size_t)(m0 + 8) * CC + col) =
                    make_ushort2(hfu(__float2half_rn(acc[fm][fn][2])),
                                 hfu(__float2half_rn(acc[fm][fn][3])));
            }
        }
    }
    #undef ISSUE
}

// ---------------------------------------------------------------------------
// greduce: sum KSPL partials of one 64-row half of a G tile, split to fp16
// hi/lo, write tile + symmetric mirror. grid (21, 16, 2), block 256.
// ---------------------------------------------------------------------------
__global__ __launch_bounds__(256)
void greduce_kernel()
{
    __shared__ float s[64][132];
    int t = blockIdx.x;
    const int b = blockIdx.y;
    const int hhalf = blockIdx.z;
    int bm = 0;
    while (t >= 6 - bm) { t -= 6 - bm; bm++; }
    const int bn = bm + t;
    const int tid = threadIdx.x;

    const float* P0 = g_Gpart + (((size_t)b * KSPL) * 21 + blockIdx.x) * 16384;
    const float* P1 = P0 + (size_t)21 * 16384;
    const float* P2 = P1 + (size_t)21 * 16384;
    const float* P3 = P2 + (size_t)21 * 16384;
    __half* Hi = g_Ghi + (size_t)b * GSZ;
    __half* Lo = g_Glo + (size_t)b * GSZ;

    const int rbase = hhalf * 64;
    for (int e4 = tid; e4 < 2048; e4 += 256) {
        const int r = e4 >> 5, c4 = e4 & 31;
        const size_t o = (size_t)(rbase + r) * 128 + c4 * 4;
        float4 a = *(const float4*)(P0 + o);
        float4 bb = *(const float4*)(P1 + o);
        float4 c = *(const float4*)(P2 + o);
        float4 d = *(const float4*)(P3 + o);
        s[r][c4 * 4 + 0] = a.x + bb.x + c.x + d.x;
        s[r][c4 * 4 + 1] = a.y + bb.y + c.y + d.y;
        s[r][c4 * 4 + 2] = a.z + bb.z + c.z + d.z;
        s[r][c4 * 4 + 3] = a.w + bb.w + c.w + d.w;
    }
    __syncthreads();

    {
        const int r = tid >> 2, cb = (tid & 3) * 32;
        const size_t rowo = (size_t)(bm * 128 + rbase + r) * CC + bn * 128 + cb;
        #pragma unroll
        for (int k = 0; k < 32; k += 8) {
            ushort hh[8], ll[8];
            #pragma unroll
            for (int j = 0; j < 8; ++j) {
                __half hb, lb; split1(s[r][cb + k + j], hb, lb);
                hh[j] = hfu(hb); ll[j] = hfu(lb);
            }
            uint4 uh, ul;
            uh.x = hh[0] | (hh[1] << 16); uh.y = hh[2] | (hh[3] << 16);
            uh.z = hh[4] | (hh[5] << 16); uh.w = hh[6] | (hh[7] << 16);
            ul.x = ll[0] | (ll[1] << 16); ul.y = ll[2] | (ll[3] << 16);
            ul.z = ll[4] | (ll[5] << 16); ul.w = ll[6] | (ll[7] << 16);
            *(uint4*)(Hi + rowo + k) = uh;
            *(uint4*)(Lo + rowo + k) = ul;
        }
    }
    if (bm != bn) {
        const int j = tid >> 1, cb = (tid & 1) * 32;
        const size_t rowo = (size_t)(bn * 128 + j) * CC + bm * 128 + rbase + cb;
        #pragma unroll
        for (int k = 0; k < 32; k += 8) {
            ushort hh[8], ll[8];
            #pragma unroll
            for (int jj = 0; jj < 8; ++jj) {
                __half hb, lb; split1(s[cb + k + jj][j], hb, lb);
                hh[jj] = hfu(hb); ll[jj] = hfu(lb);
            }
            uint4 uh, ul;
            uh.x = hh[0] | (hh[1] << 16); uh.y = hh[2] | (hh[3] << 16);
            uh.z = hh[4] | (hh[5] << 16); uh.w = hh[6] | (hh[7] << 16);
            ul.x = ll[0] | (ll[1] << 16); ul.y = ll[2] | (ll[3] << 16);
            ul.z = ll[4] | (ll[5] << 16); ul.w = ll[6] | (ll[7] << 16);
            *(uint4*)(Hi + rowo + k) = uh;
            *(uint4*)(Lo + rowo + k) = ul;
        }
    }
}

// ---------------------------------------------------------------------------
// logits + softmax per (b,h), 2 d-halves. grid (128, 2).
// ---------------------------------------------------------------------------
#define WOFF 1600
__global__ __launch_bounds__(256)
void logits_kernel(const float* __restrict__ w_qkv, const float* __restrict__ b_qkv)
{
    const int bh = blockIdx.x;
    const int yh = blockIdx.y;
    const int b = bh >> 3, h = bh & 7;

    __shared__ float buf[WOFF + 3104];
    __shared__ float bqs[48], ws_[48], bks[96], us_[96];

    const int tid = threadIdx.x;
    const int tx = tid & 15;
    const int ty = tid >> 4;

    if (tid < 48) {
        bqs[tid] = b_qkv[h * DD + yh * 48 + tid];
        ws_[tid] = g_U[b * 1536 + h * DD + yh * 48 + tid];
    }
    if (tid < 96) {
        bks[tid] = b_qkv[CC + h * DD + tid];
        us_[tid] = g_U[b * 1536 + CC + h * DD + tid];
    }

    const float* Tb = g_T + (size_t)b * GSZ + (size_t)(h * DD + yh * 48) * CC;
    const float* Wk = w_qkv + (size_t)(CC + h * DD) * CC;

    float acc[3][6];
    #pragma unroll
    for (int i = 0; i < 3; i++)
        #pragma unroll
        for (int j = 0; j < 6; j++) acc[i][j] = 0.f;

    for (int c0 = 0; c0 < CC; c0 += 32) {
        __syncthreads();
        for (int id = tid; id < 384 + 768; id += 256) {
            if (id < 384) {
                const int row = id >> 3, f4 = id & 7;
                float4 tv = *(const float4*)(Tb + (size_t)row * CC + c0 + f4 * 4);
                buf[(f4 * 4 + 0) * 49 + row] = tv.x;
                buf[(f4 * 4 + 1) * 49 + row] = tv.y;
                buf[(f4 * 4 + 2) * 49 + row] = tv.z;
                buf[(f4 * 4 + 3) * 49 + row] = tv.w;
            } else {
                const int id2 = id - 384;
                const int row = id2 >> 3, f4 = id2 & 7;
                float4 kv = *(const float4*)(Wk + (size_t)row * CC + c0 + f4 * 4);
                buf[WOFF + (f4 * 4 + 0) * 97 + row] = kv.x;
                buf[WOFF + (f4 * 4 + 1) * 97 + row] = kv.y;
                buf[WOFF + (f4 * 4 + 2) * 97 + row] = kv.z;
                buf[WOFF + (f4 * 4 + 3) * 97 + row] = kv.w;
            }
        }
        __syncthreads();
        #pragma unroll 8
        for (int kk = 0; kk < 32; ++kk) {
            float qr[3], kr[6];
            #pragma unroll
            for (int i = 0; i < 3; i++)
                qr[i] = buf[kk * 49 + ty * 3 + i];
            #pragma unroll
            for (int j = 0; j < 6; j++)
                kr[j] = buf[WOFF + kk * 97 + tx * 6 + j];
            #pragma unroll
            for (int i = 0; i < 3; i++)
                #pragma unroll
                for (int j = 0; j < 6; j++)
                    acc[i][j] = fmaf(qr[i], kr[j], acc[i][j]);
        }
    }
    __syncthreads();

    const float scale = 0.015625f;
    #pragma unroll
    for (int i = 0; i < 3; i++) {
        const int dl = ty * 3 + i;
        #pragma unroll
        for (int j = 0; j < 6; j++) {
            const int e = tx * 6 + j;
            float v = acc[i][j] + bqs[dl] * us_[e] + bks[e] * ws_[dl]
                      + 4096.f * bqs[dl] * bks[e];
            buf[dl * 96 + e] = v * scale;
        }
    }
    __syncthreads();

    const int wid = tid >> 5, lane = tid & 31;
    for (int r = wid; r < 48; r += 8) {
        float v0 = buf[r * 96 + lane];
        float v1 = buf[r * 96 + 32 + lane];
        float v2 = buf[r * 96 + 64 + lane];
        float m = fmaxf(v0, fmaxf(v1, v2));
        #pragma unroll
        for (int off = 16; off > 0; off >>= 1)
            m = fmaxf(m, __shfl_xor_sync(0xffffffffu, m, off));
        float e0 = expf(v0 - m), e1 = expf(v1 - m), e2 = expf(v2 - m);
        float s = e0 + e1 + e2;
        #pragma unroll
        for (int off = 16; off > 0; off >>= 1)
            s += __shfl_xor_sync(0xffffffffu, s, off);
        const float inv = 1.f / s;
        float* arow = g_attn + ((size_t)bh * 96 + yh * 48 + r) * 96;
        arow[lane]      = e0 * inv;
        arow[lane + 32] = e1 * inv;
        arow[lane + 64] = e2 * inv;
    }
}

// ---------------------------------------------------------------------------
// MT_b[c, h*96+d] = sum_e A_bh[d,e] Wv[h*96+e, c]  (fp16 hi only); grid (6,128)
// ---------------------------------------------------------------------------
__global__ __launch_bounds__(256)
void mt_kernel(const float* __restrict__ w_qkv, const float* __restrict__ b_qkv)
{
    const int c0 = blockIdx.x * 128;
    const int bh = blockIdx.y;
    const int b = bh >> 3, h = bh & 7;

    __shared__ float As[96 * 97];
    __shared__ float Ws[16 * 132];
    __shared__ float bvs[96];

    const int tid = threadIdx.x;
    const int tx = tid & 15;
    const int ty = tid >> 4;

    const float* asrc = g_attn + (size_t)bh * 9216;
    for (int id = tid; id < 9216; id += 256) {
        const int r = id / 96, c = id - r * 96;
        As[r * 97 + c] = asrc[id];
    }
    if (tid < 96) bvs[tid] = b_qkv[2 * CC + h * DD + tid];
    __syncthreads();

    if (blockIdx.x == 0 && tid < 96) {
        float rv = 0.f;
        #pragma unroll 4
        for (int e = 0; e < 96; ++e) rv += As[tid * 97 + e] * bvs[e];
        g_r[b * CC + h * DD + tid] = rv;
    }

    const float* Wv = w_qkv + (size_t)(2 * CC + h * DD) * CC;
    __half* MTh = g_MThi + (size_t)b * GSZ;

    float acc[8][6];
    #pragma unroll
    for (int i = 0; i < 8; i++)
        #pragma unroll
        for (int j = 0; j < 6; j++) acc[i][j] = 0.f;

    for (int e0 = 0; e0 < 96; e0 += 16) {
        if (e0) __syncthreads();
        #pragma unroll
        for (int t = 0; t < 2; ++t) {
            const int id = tid + t * 256;
            const int e = id >> 5, f4 = id & 31;
            float4 v = *(const float4*)(Wv + (size_t)(e0 + e) * CC + c0 + f4 * 4);
            *(float4*)&Ws[e * 132 + f4 * 4] = v;
        }
        __syncthreads();
        #pragma unroll
        for (int e = 0; e < 16; ++e) {
            float vv[8], aa[6];
            #pragma unroll
            for (int i = 0; i < 8; i++) vv[i] = Ws[e * 132 + ty * 8 + i];
            #pragma unroll
            for (int j = 0; j < 6; j++) aa[j] = As[(tx * 6 + j) * 97 + e0 + e];
            #pragma unroll
            for (int i = 0; i < 8; i++)
                #pragma unroll
                for (int j = 0; j < 6; j++)
                    acc[i][j] = fmaf(vv[i], aa[j], acc[i][j]);
        }
    }
    #pragma unroll
    for (int i = 0; i < 8; i++) {
        const int c = c0 + ty * 8 + i;
        const size_t base = (size_t)c * CC + h * DD + tx * 6;
        #pragma unroll
        for (int j = 0; j < 6; j += 2) {
            *(ushort2*)(MTh + base + j) =
                make_ushort2(hfu(__float2half_rn(acc[i][j])),
                             hfu(__float2half_rn(acc[i][j + 1])));
        }
    }
}

// ---------------------------------------------------------------------------
extern "C" void kernel_launch(void* const* d_in, const int* in_sizes, int n_in,
                              void* d_out, int out_size)
{
    const float* x      = (const float*)d_in[0];
    const float* w_qkv  = (const float*)d_in[1];
    const float* b_qkv  = (const float*)d_in[2];
    const float* w_proj = (const float*)d_in[3];
    const float* b_proj = (const float*)d_in[4];
    float*       out    = (float*)d_out;

    cudaFuncSetAttribute(tgemm_kernel<0>,
                         cudaFuncAttributeMaxDynamicSharedMemorySize, SMEM_012);
    cudaFuncSetAttribute(tgemm_kernel<1>,
                         cudaFuncAttributeMaxDynamicSharedMemorySize, SMEM_012);
    cudaFuncSetAttribute(tgemm_kernel<2>,
                         cudaFuncAttributeMaxDynamicSharedMemorySize, SMEM_3);
    cudaFuncSetAttribute(tgemm_kernel<3>,
                         cudaFuncAttributeMaxDynamicSharedMemorySize, SMEM_3);

    // 0) splits + transposed splits + fused column sums; weight splits + colsum
    transpose_split_kernel<<<dim3(12, 1024), 256>>>(x);
    prep_kernel<<<1168, 256>>>((const float4*)w_qkv, (const float4*)w_proj);

    // 1) G partials (2-PASS, K-split x4, diag dedup) + reduce/split/mirror
    tgemm_kernel<0><<<dim3(21, KSPL, BB), 256, SMEM_012>>>(nullptr);
    greduce_kernel<<<dim3(21, BB, 2), 256>>>();

    // 2) T_b = Wq @ G_b  (3-pass)
    tgemm_kernel<1><<<dim3(6, 6, BB), 256, SMEM_012>>>(nullptr);

    // 3) rank-1 correction dots, logits + softmax (d-split x2)
    uw_kernel<<<dim3(192, BB), 256>>>(w_qkv);
    logits_kernel<<<dim3(BB * HH, 2), 256>>>(w_qkv, b_qkv);

    // 4) MT_b = (A @ Wv)^T stacked (fp16 hi only); r_bh
    mt_kernel<<<dim3(6, BB * HH), 256>>>(w_qkv, b_qkv);

    // 5) P_b = Wp_hi @ MT_hi (single-pass, 5-stage); fused output bias
    biasf_kernel<<<dim3(96, BB), 256>>>(w_proj, b_proj);
    tgemm_kernel<2><<<dim3(6, 6, BB), 256, SMEM_3>>>(nullptr);

    // 6) out = Xhi @ Phi^T + biasf   (single-pass fp16, 5-stage)
    tgemm_kernel<3><<<dim3(6, 512, 1), 256, SMEM_3>>>(out);
}

// round 15
// speedup vs baseline: 1.1352x; 1.0065x over previous
#include <cuda_runtime.h>
#include <cuda_fp16.h>
#include <cstdint>

// Problem constants
#define BB   16
#define NT   4096
#define CC   768
#define HH   8
#define DD   96
#define MM   (BB * NT)          // 65536
#define GSZ  (768 * 768)        // 589824
#define KSPL 4                  // K-split for the G GEMM

// ---------------------------------------------------------------------------
// Scratch (__device__ globals)
// ---------------------------------------------------------------------------
__device__ __half g_xhi[(size_t)MM * CC];
__device__ __half g_xThi[(size_t)MM * CC], g_xTlo[(size_t)MM * CC]; // [b,c,n]
__device__ float g_Gpart[(size_t)BB * KSPL * 21 * 16384];           // fp32 partials
__device__ __half g_Ghi[BB * GSZ], g_Glo[BB * GSZ];
__device__ float g_T[BB * GSZ];
__device__ float g_attn[BB * HH * DD * DD];
__device__ __half g_MThi[BB * GSZ];                     // [b, c, h*96+d]
__device__ __half g_Phi[BB * GSZ];
__device__ __half g_wqh[GSZ], g_wql[GSZ];
__device__ __half g_wph[GSZ];
__device__ float g_s[BB * CC];
__device__ float g_part2[1024 * CC];                    // per-64-row-block colsums
__device__ float g_U[BB * 1536];
__device__ float g_r[BB * CC];
__device__ float g_biasf[BB * CC];

// ---------------------------------------------------------------------------
// PTX helpers (target-agnostic)
// ---------------------------------------------------------------------------
__device__ __forceinline__ uint32_t smem_u32(const void* p) {
    uint32_t a;
    asm("{ .reg .u64 t; cvta.to.shared.u64 t, %1; cvt.u32.u64 %0, t; }"
        : "=r"(a) : "l"(p));
    return a;
}
__device__ __forceinline__ void ldsm_x4(uint32_t* r, uint32_t addr) {
    asm volatile("ldmatrix.sync.aligned.m8n8.x4.shared.b16 {%0,%1,%2,%3}, [%4];"
                 : "=r"(r[0]), "=r"(r[1]), "=r"(r[2]), "=r"(r[3]) : "r"(addr));
}
__device__ __forceinline__ void mma16816(float* c, const uint32_t* a, const uint32_t* b) {
    asm volatile(
        "mma.sync.aligned.m16n8k16.row.col.f32.f16.f16.f32 "
        "{%0,%1,%2,%3}, {%4,%5,%6,%7}, {%8,%9}, {%0,%1,%2,%3};"
        : "+f"(c[0]), "+f"(c[1]), "+f"(c[2]), "+f"(c[3])
        : "r"(a[0]), "r"(a[1]), "r"(a[2]), "r"(a[3]), "r"(b[0]), "r"(b[1]));
}
__device__ __forceinline__ void cp16(uint32_t dst, const void* src) {
    asm volatile("cp.async.cg.shared.global [%0], [%1], 16;"
                 :: "r"(dst), "l"(src) : "memory");
}
__device__ __forceinline__ void cp_commit() {
    asm volatile("cp.async.commit_group;" ::: "memory");
}
template <int N>
__device__ __forceinline__ void cp_wait() {
    asm volatile("cp.async.wait_group %0;" :: "n"(N) : "memory");
}
__device__ __forceinline__ void split1(float v, __half& h, __half& l) {
    h = __float2half_rn(v);
    l = __float2half_rn(v - __half2float(h));
}
__device__ __forceinline__ ushort hfu(__half v) { return __half_as_ushort(v); }

// ---------------------------------------------------------------------------
// transpose_split: x -> row-major hi, per-batch transposed hi/lo,
// AND per-block column partial sums (fused colsum).
// ---------------------------------------------------------------------------
__global__ __launch_bounds__(256)
void transpose_split_kernel(const float* __restrict__ x)
{
    __shared__ float tile[64 * 65];
    __shared__ float colp[4][64];
    const int tid = threadIdx.x;
    const int C0 = blockIdx.x * 64;
    const int R0 = blockIdx.y * 64;

    #pragma unroll
    for (int t = 0; t < 4; ++t) {
        const int id = tid + t * 256;
        const int r = id >> 4, f4 = id & 15;
        float4 v = *(const float4*)(x + (size_t)(R0 + r) * CC + C0 + f4 * 4);
        tile[r * 65 + f4 * 4 + 0] = v.x;
        tile[r * 65 + f4 * 4 + 1] = v.y;
        tile[r * 65 + f4 * 4 + 2] = v.z;
        tile[r * 65 + f4 * 4 + 3] = v.w;
    }
    __syncthreads();

    {
        const int c = tid & 63, q = tid >> 6;
        float s = 0.f;
        #pragma unroll
        for (int r = 0; r < 16; ++r) s += tile[(q * 16 + r) * 65 + c];
        colp[q][c] = s;
    }
    __syncthreads();
    if (tid < 64)
        g_part2[(size_t)blockIdx.y * CC + C0 + tid] =
            colp[0][tid] + colp[1][tid] + colp[2][tid] + colp[3][tid];

    #pragma unroll
    for (int t = 0; t < 2; ++t) {
        const int id = tid + t * 256;
        const int r = id >> 3, g = id & 7;
        ushort h[8];
        #pragma unroll
        for (int j = 0; j < 8; j++)
            h[j] = hfu(__float2half_rn(tile[r * 65 + g * 8 + j]));
        uint4 uh;
        uh.x = h[0] | (h[1] << 16); uh.y = h[2] | (h[3] << 16);
        uh.z = h[4] | (h[5] << 16); uh.w = h[6] | (h[7] << 16);
        const size_t off = (size_t)(R0 + r) * CC + C0 + g * 8;
        *(uint4*)(g_xhi + off) = uh;
    }

    const int bb = R0 >> 12;
    const int n0 = R0 & 4095;
    #pragma unroll
    for (int t = 0; t < 2; ++t) {
        const int id = tid + t * 256;
        const int c = id >> 3, g = id & 7;
        ushort h[8], l[8];
        #pragma unroll
        for (int j = 0; j < 8; j++) {
            __half hb, lb; split1(tile[(g * 8 + j) * 65 + c], hb, lb);
            h[j] = hfu(hb); l[j] = hfu(lb);
        }
        uint4 uh, ul;
        uh.x = h[0] | (h[1] << 16); uh.y = h[2] | (h[3] << 16);
        uh.z = h[4] | (h[5] << 16); uh.w = h[6] | (h[7] << 16);
        ul.x = l[0] | (l[1] << 16); ul.y = l[2] | (l[3] << 16);
        ul.z = l[4] | (l[5] << 16); ul.w = l[6] | (l[7] << 16);
        const size_t off = ((size_t)bb * CC + C0 + c) * NT + n0 + g * 8;
        *(uint4*)(g_xThi + off) = uh;
        *(uint4*)(g_xTlo + off) = ul;
    }
}

// ---------------------------------------------------------------------------
// prep: blocks [0,576) wq hi/lo split; [576,1152) wp hi split;
//       blocks [1152,1168) colsum reduction.
// ---------------------------------------------------------------------------
__global__ __launch_bounds__(256)
void prep_kernel(const float4* __restrict__ wq, const float4* __restrict__ wp)
{
    const int blk = blockIdx.x;
    const int tid = threadIdx.x;
    if (blk < 576) {
        const int j = blk * 256 + tid;
        float4 v = wq[j];
        float a[4] = {v.x, v.y, v.z, v.w};
        ushort h[4], l[4];
        #pragma unroll
        for (int t = 0; t < 4; t++) {
            __half hb, lb; split1(a[t], hb, lb);
            h[t] = hfu(hb); l[t] = hfu(lb);
        }
        ((ushort4*)g_wqh)[j] = make_ushort4(h[0], h[1], h[2], h[3]);
        ((ushort4*)g_wql)[j] = make_ushort4(l[0], l[1], l[2], l[3]);
    } else if (blk < 1152) {
        const int j = (blk - 576) * 256 + tid;
        float4 v = wp[j];
        ushort h[4];
        h[0] = hfu(__float2half_rn(v.x));
        h[1] = hfu(__float2half_rn(v.y));
        h[2] = hfu(__float2half_rn(v.z));
        h[3] = hfu(__float2half_rn(v.w));
        ((ushort4*)g_wph)[j] = make_ushort4(h[0], h[1], h[2], h[3]);
    } else {
        const int b = blk - 1152;
        #pragma unroll
        for (int p = 0; p < 3; ++p) {
            const int c = p * 256 + tid;
            float s = 0.f;
            for (int k = 0; k < 64; ++k)
                s += g_part2[(size_t)(b * 64 + k) * CC + c];
            g_s[b * CC + c] = s;
        }
    }
}

// ---------------------------------------------------------------------------
// U[b][row] = dot(w_qkv[row], s_b), rows 0..1535
// ---------------------------------------------------------------------------
__global__ __launch_bounds__(256)
void uw_kernel(const float* __restrict__ w_qkv)
{
    __shared__ float ss[CC];
    const int b = blockIdx.y, tid = threadIdx.x;
    #pragma unroll
    for (int p = 0; p < 3; ++p) ss[p * 256 + tid] = g_s[b * CC + p * 256 + tid];
    __syncthreads();
    const int row = blockIdx.x * 8 + (tid >> 5);
    const int lane = tid & 31;
    const float* wr = w_qkv + (size_t)row * CC;
    float acc = 0.f;
    #pragma unroll
    for (int k = 0; k < 24; ++k) acc += wr[lane + k * 32] * ss[lane + k * 32];
    #pragma unroll
    for (int off = 16; off > 0; off >>= 1)
        acc += __shfl_xor_sync(0xffffffffu, acc, off);
    if (lane == 0) g_U[b * 1536 + row] = acc;
}

// ---------------------------------------------------------------------------
// biasf[b][j] = b_proj[j] + dot(w_proj[j], r_b)
// ---------------------------------------------------------------------------
__global__ __launch_bounds__(256)
void biasf_kernel(const float* __restrict__ w_proj, const float* __restrict__ b_proj)
{
    __shared__ float rr[CC];
    const int b = blockIdx.y, tid = threadIdx.x;
    #pragma unroll
    for (int p = 0; p < 3; ++p) rr[p * 256 + tid] = g_r[b * CC + p * 256 + tid];
    __syncthreads();
    const int j = blockIdx.x * 8 + (tid >> 5);
    const int lane = tid & 31;
    const float* wr = w_proj + (size_t)j * CC;
    float acc = 0.f;
    #pragma unroll
    for (int k = 0; k < 24; ++k) acc += wr[lane + k * 32] * rr[lane + k * 32];
    #pragma unroll
    for (int off = 16; off > 0; off >>= 1)
        acc += __shfl_xor_sync(0xffffffffu, acc, off);
    if (lane == 0) g_biasf[b * CC + j] = b_proj[j] + acc;
}

// ---------------------------------------------------------------------------
// HMMA fp16-split GEMM, templated on MODE (R14 numerics, unchanged).
//   MODE 0: Gpart = Xhi^T @ (Xhi + Xlo)  (2-PASS, K-split, fp32 out)
//           grid (21, KSPL, BB); diag: Bh deduped onto A slot, Bl in slot 1
//   MODE 1: T_b = Wq @ G_b       (K=768, 3-pass, fp32 out)
//   MODE 2: P_b = Wp_hi @ MT_hi  (K=768, 1-pass, fp16 hi out, 5-stage)
//   MODE 3: out = X_hi @ P_hi^T + biasf  (K=768, 1-pass, 5-stage)
// ---------------------------------------------------------------------------
#define SROW 80
#define TILE_B (128 * SROW)
#define SMEM_012 (2 * 4 * TILE_B)   // 81920 (modes 0,1)
#define SMEM_3   (5 * 2 * TILE_B)   // 102400 (modes 2,3)

template <int MODE>
__global__ __launch_bounds__(256, 2)
void tgemm_kernel(float* __restrict__ Cp)
{
    constexpr bool SINGLE = (MODE >= 2);
    constexpr int NTILES = SINGLE ? 2 : 4;
    constexpr int NSTAGE = SINGLE ? 5 : 2;
    constexpr int STAGE_B = NTILES * TILE_B;

    int bm = blockIdx.y, bn = blockIdx.x;
    int b = blockIdx.z;
    int ksplit = 0;
    if (MODE == 0) {
        int t = blockIdx.x;
        bm = 0;
        while (t >= 6 - bm) { t -= 6 - bm; bm++; }
        bn = bm + t;
        ksplit = blockIdx.y;
    }
    const bool diag = (MODE == 0) && (bm == bn);

    const __half *Ah, *Al = nullptr, *Wh, *Wl = nullptr;
    constexpr int KROW  = (MODE == 0) ? 4096 : 768;
    constexpr int KITER = (MODE == 0) ? 1024 : 768;

    if (MODE == 0) {
        const size_t ab = ((size_t)b * CC + bm * 128) * NT + ksplit * KITER;
        const size_t wb = ((size_t)b * CC + bn * 128) * NT + ksplit * KITER;
        Ah = g_xThi + ab;                    // A = Xhi(bm) only (2-pass)
        Wh = g_xThi + wb; Wl = g_xTlo + wb;  // B = Xhi(bn), Xlo(bn)
    } else if (MODE == 1) {
        Ah = g_wqh + (size_t)bm * 128 * CC; Al = g_wql + (size_t)bm * 128 * CC;
        const size_t wb = (size_t)b * GSZ + (size_t)bn * 128 * CC;
        Wh = g_Ghi + wb; Wl = g_Glo + wb;
    } else if (MODE == 2) {
        Ah = g_wph + (size_t)bm * 128 * CC;
        Wh = g_MThi + (size_t)b * GSZ + (size_t)bn * 128 * CC;
    } else {
        b = bm >> 5;
        Ah = g_xhi + (size_t)bm * 128 * CC;
        Wh = g_Phi + (size_t)b * GSZ + (size_t)bn * 128 * CC;
    }

    extern __shared__ char smem[];
    const uint32_t ubase = smem_u32(smem);

    const int tid  = threadIdx.x;
    const int wid  = tid >> 5;
    const int lane = tid & 31;
    const int wm   = wid & 1;
    const int wn   = wid >> 1;

    const int cr = tid >> 2;
    const int cg = tid & 3;

    const uint32_t boff = SINGLE ? TILE_B : (diag ? 0u : 2u * TILE_B);

    #define ISSUE(s) do { \
        const uint32_t sb_ = ubase + ((s) % NSTAGE) * STAGE_B; \
        const int kof_ = (s) * 32; \
        _Pragma("unroll") \
        for (int t_ = 0; t_ < 2; ++t_) { \
            const int r_ = cr + t_ * 64; \
            const size_t off_ = (size_t)r_ * KROW + kof_ + cg * 8; \
            const uint32_t d_ = sb_ + r_ * SROW + cg * 16; \
            cp16(d_ + 0 * TILE_B, Ah + off_); \
            if (SINGLE) { \
                cp16(d_ + TILE_B, Wh + off_); \
            } else if (MODE == 0) { \
                if (diag) { \
                    cp16(d_ + 1 * TILE_B, Wl + off_); \
                } else { \
                    cp16(d_ + 2 * TILE_B, Wh + off_); \
                    cp16(d_ + 3 * TILE_B, Wl + off_); \
                } \
            } else { \
                cp16(d_ + 1 * TILE_B, Al + off_); \
                cp16(d_ + 2 * TILE_B, Wh + off_); \
                cp16(d_ + 3 * TILE_B, Wl + off_); \
            } \
        } \
        cp_commit(); \
    } while (0)

    float acc[4][4][4];
    #pragma unroll
    for (int i = 0; i < 4; i++)
        #pragma unroll
        for (int j = 0; j < 4; j++)
            #pragma unroll
            for (int q = 0; q < 4; q++) acc[i][j][q] = 0.f;

    const int laneRA = lane & 15;
    const int laneGA = lane >> 4;
    const int laneRB = (lane & 7) | ((lane >> 4) << 3);
    const int laneGB = (lane >> 3) & 1;

    const int NK = KITER >> 5;

    if (SINGLE) { ISSUE(0); ISSUE(1); ISSUE(2); ISSUE(3); }
    else        { ISSUE(0); ISSUE(1); }

    for (int kb = 0; kb < NK; ++kb) {
        if (SINGLE) {
            if (kb + 4 <= NK) cp_wait<3>();
            else if (kb + 3 <= NK) cp_wait<2>();
            else if (kb + 2 <= NK) cp_wait<1>();
            else cp_wait<0>();
            __syncthreads();
            if (kb + 4 < NK) ISSUE(kb + 4);   // slot (kb-1)%5: readers done
        } else {
            if (kb + 1 < NK) cp_wait<1>(); else cp_wait<0>();
            __syncthreads();
        }

        const uint32_t sb = ubase + (kb % NSTAGE) * STAGE_B;
        const uint32_t aBase = sb + (wm * 64 + laneRA) * SROW + laneGA * 16;
        const uint32_t bBase = sb + boff + (wn * 32 + laneRB) * SROW + laneGB * 16;

        #pragma unroll
        for (int ks = 0; ks < 2; ++ks) {
            const uint32_t ko = ks * 32;
            uint32_t bh[4][2], bl[4][2];
            #pragma unroll
            for (int fp = 0; fp < 2; fp++) {
                uint32_t q[4];
                ldsm_x4(q, bBase + fp * (16 * SROW) + ko);
                bh[2 * fp][0] = q[0]; bh[2 * fp][1] = q[1];
                bh[2 * fp + 1][0] = q[2]; bh[2 * fp + 1][1] = q[3];
                if (!SINGLE) {
                    ldsm_x4(q, bBase + TILE_B + fp * (16 * SROW) + ko);
                    bl[2 * fp][0] = q[0]; bl[2 * fp][1] = q[1];
                    bl[2 * fp + 1][0] = q[2]; bl[2 * fp + 1][1] = q[3];
                }
            }
            #pragma unroll
            for (int fm = 0; fm < 4; fm++) {
                uint32_t ah[4], al[4];
                ldsm_x4(ah, aBase + fm * (16 * SROW) + ko);
                if (MODE == 1)
                    ldsm_x4(al, aBase + TILE_B + fm * (16 * SROW) + ko);
                #pragma unroll
                for (int fn = 0; fn < 4; fn++) {
                    mma16816(acc[fm][fn], ah, bh[fn]);
                    if (!SINGLE) mma16816(acc[fm][fn], ah, bl[fn]);
                    if (MODE == 1) mma16816(acc[fm][fn], al, bh[fn]);
                }
            }
        }

        if (!SINGLE && kb + 2 < NK) {
            __syncthreads();      // all warps done reading this buffer
            ISSUE(kb + 2);
        }
    }

    const int gid4 = lane >> 2;
    const int tig  = lane & 3;

    if (MODE == 1 || MODE == 3) {
        float* C = (MODE == 1) ? (g_T + (size_t)b * GSZ) : Cp;
        const float* bias = (MODE == 3) ? (g_biasf + b * CC) : nullptr;
        #pragma unroll
        for (int fm = 0; fm < 4; fm++) {
            const int m0 = bm * 128 + wm * 64 + fm * 16 + gid4;
            #pragma unroll
            for (int fn = 0; fn < 4; fn++) {
                const int col = bn * 128 + wn * 32 + fn * 8 + tig * 2;
                float bx = 0.f, by = 0.f;
                if (MODE == 3) { bx = bias[col]; by = bias[col + 1]; }
                float2 o;
                o.x = acc[fm][fn][0] + bx; o.y = acc[fm][fn][1] + by;
                *(float2*)(C + (size_t)m0 * CC + col) = o;
                o.x = acc[fm][fn][2] + bx; o.y = acc[fm][fn][3] + by;
                *(float2*)(C + (size_t)(m0 + 8) * CC + col) = o;
            }
        }
    } else if (MODE == 0) {
        float* P = g_Gpart + (((size_t)b * KSPL + ksplit) * 21 + blockIdx.x) * 16384;
        #pragma unroll
        for (int fm = 0; fm < 4; fm++) {
            const int m0 = wm * 64 + fm * 16 + gid4;
            #pragma unroll
            for (int fn = 0; fn < 4; fn++) {
                const int col = wn * 32 + fn * 8 + tig * 2;
                *(float2*)(P + (size_t)m0 * 128 + col) =
                    make_float2(acc[fm][fn][0], acc[fm][fn][1]);
                *(float2*)(P + (size_t)(m0 + 8) * 128 + col) =
                    make_float2(acc[fm][fn][2], acc[fm][fn][3]);
            }
        }
    } else {   // MODE 2: P hi only
        __half* Hi = g_Phi + (size_t)b * GSZ;
        #pragma unroll
        for (int fm = 0; fm < 4; fm++) {
            const int m0 = bm * 128 + wm * 64 + fm * 16 + gid4;
            #pragma unroll
            for (int fn = 0; fn < 4; fn++) {
                const int col = bn * 128 + wn * 32 + fn * 8 + tig * 2;
                *(ushort2*)(Hi + (size_t)m0 * CC + col) =
                    make_ushort2(hfu(__float2half_rn(acc[fm][fn][0])),
                                 hfu(__float2half_rn(acc[fm][fn][1])));
                *(ushort2*)(Hi + (size_t)(m0 + 8) * CC + col) =
                    make_ushort2(hfu(__float2half_rn(acc[fm][fn][2])),
                                 hfu(__float2half_rn(acc[fm][fn][3])));
            }
        }
    }
    #undef ISSUE
}

// ---------------------------------------------------------------------------
// greduce: sum KSPL partials of one 32-row QUARTER of a G tile, split to fp16
// hi/lo, write tile + symmetric mirror. grid (21, 16, 4), block 256.
// (same fp32 add order as before -> bit-identical results, 2x parallelism)
// ---------------------------------------------------------------------------
__global__ __launch_bounds__(256)
void greduce_kernel()
{
    __shared__ float s[32][132];
    int t = blockIdx.x;
    const int b = blockIdx.y;
    const int qz = blockIdx.z;           // 0..3 quarter (32 rows)
    int bm = 0;
    while (t >= 6 - bm) { t -= 6 - bm; bm++; }
    const int bn = bm + t;
    const int tid = threadIdx.x;

    const float* P0 = g_Gpart + (((size_t)b * KSPL) * 21 + blockIdx.x) * 16384;
    const float* P1 = P0 + (size_t)21 * 16384;
    const float* P2 = P1 + (size_t)21 * 16384;
    const float* P3 = P2 + (size_t)21 * 16384;
    __half* Hi = g_Ghi + (size_t)b * GSZ;
    __half* Lo = g_Glo + (size_t)b * GSZ;

    const int rbase = qz * 32;
    #pragma unroll
    for (int e4 = tid; e4 < 1024; e4 += 256) {
        const int r = e4 >> 5, c4 = e4 & 31;
        const size_t o = (size_t)(rbase + r) * 128 + c4 * 4;
        float4 a = *(const float4*)(P0 + o);
        float4 bb = *(const float4*)(P1 + o);
        float4 c = *(const float4*)(P2 + o);
        float4 d = *(const float4*)(P3 + o);
        s[r][c4 * 4 + 0] = a.x + bb.x + c.x + d.x;
        s[r][c4 * 4 + 1] = a.y + bb.y + c.y + d.y;
        s[r][c4 * 4 + 2] = a.z + bb.z + c.z + d.z;
        s[r][c4 * 4 + 3] = a.w + bb.w + c.w + d.w;
    }
    __syncthreads();

    // direct write: 32 rows x 128 cols (8 threads/row, 16 cols each)
    {
        const int r = tid >> 3, cb = (tid & 7) * 16;
        const size_t rowo = (size_t)(bm * 128 + rbase + r) * CC + bn * 128 + cb;
        #pragma unroll
        for (int k = 0; k < 16; k += 8) {
            ushort hh[8], ll[8];
            #pragma unroll
            for (int j = 0; j < 8; ++j) {
                __half hb, lb; split1(s[r][cb + k + j], hb, lb);
                hh[j] = hfu(hb); ll[j] = hfu(lb);
            }
            uint4 uh, ul;
            uh.x = hh[0] | (hh[1] << 16); uh.y = hh[2] | (hh[3] << 16);
            uh.z = hh[4] | (hh[5] << 16); uh.w = hh[6] | (hh[7] << 16);
            ul.x = ll[0] | (ll[1] << 16); ul.y = ll[2] | (ll[3] << 16);
            ul.z = ll[4] | (ll[5] << 16); ul.w = ll[6] | (ll[7] << 16);
            *(uint4*)(Hi + rowo + k) = uh;
            *(uint4*)(Lo + rowo + k) = ul;
        }
    }
    // mirror write: 128 rows x 32 cols (2 threads/row, 16 cols each)
    if (bm != bn) {
        const int j = tid >> 1, cb = (tid & 1) * 16;
        const size_t rowo = (size_t)(bn * 128 + j) * CC + bm * 128 + rbase + cb;
        #pragma unroll
        for (int k = 0; k < 16; k += 8) {
            ushort hh[8], ll[8];
            #pragma unroll
            for (int jj = 0; jj < 8; ++jj) {
                __half hb, lb; split1(s[cb + k + jj][j], hb, lb);
                hh[jj] = hfu(hb); ll[jj] = hfu(lb);
            }
            uint4 uh, ul;
            uh.x = hh[0] | (hh[1] << 16); uh.y = hh[2] | (hh[3] << 16);
            uh.z = hh[4] | (hh[5] << 16); uh.w = hh[6] | (hh[7] << 16);
            ul.x = ll[0] | (ll[1] << 16); ul.y = ll[2] | (ll[3] << 16);
            ul.z = ll[4] | (ll[5] << 16); ul.w = ll[6] | (ll[7] << 16);
            *(uint4*)(Hi + rowo + k) = uh;
            *(uint4*)(Lo + rowo + k) = ul;
        }
    }
}

// ---------------------------------------------------------------------------
// logits + softmax per (b,h), 2 d-halves. grid (128, 2).
// ---------------------------------------------------------------------------
#define WOFF 1600
__global__ __launch_bounds__(256)
void logits_kernel(const float* __restrict__ w_qkv, const float* __restrict__ b_qkv)
{
    const int bh = blockIdx.x;
    const int yh = blockIdx.y;
    const int b = bh >> 3, h = bh & 7;

    __shared__ float buf[WOFF + 3104];
    __shared__ float bqs[48], ws_[48], bks[96], us_[96];

    const int tid = threadIdx.x;
    const int tx = tid & 15;
    const int ty = tid >> 4;

    if (tid < 48) {
        bqs[tid] = b_qkv[h * DD + yh * 48 + tid];
        ws_[tid] = g_U[b * 1536 + h * DD + yh * 48 + tid];
    }
    if (tid < 96) {
        bks[tid] = b_qkv[CC + h * DD + tid];
        us_[tid] = g_U[b * 1536 + CC + h * DD + tid];
    }

    const float* Tb = g_T + (size_t)b * GSZ + (size_t)(h * DD + yh * 48) * CC;
    const float* Wk = w_qkv + (size_t)(CC + h * DD) * CC;

    float acc[3][6];
    #pragma unroll
    for (int i = 0; i < 3; i++)
        #pragma unroll
        for (int j = 0; j < 6; j++) acc[i][j] = 0.f;

    for (int c0 = 0; c0 < CC; c0 += 32) {
        __syncthreads();
        for (int id = tid; id < 384 + 768; id += 256) {
            if (id < 384) {
                const int row = id >> 3, f4 = id & 7;
                float4 tv = *(const float4*)(Tb + (size_t)row * CC + c0 + f4 * 4);
                buf[(f4 * 4 + 0) * 49 + row] = tv.x;
                buf[(f4 * 4 + 1) * 49 + row] = tv.y;
                buf[(f4 * 4 + 2) * 49 + row] = tv.z;
                buf[(f4 * 4 + 3) * 49 + row] = tv.w;
            } else {
                const int id2 = id - 384;
                const int row = id2 >> 3, f4 = id2 & 7;
                float4 kv = *(const float4*)(Wk + (size_t)row * CC + c0 + f4 * 4);
                buf[WOFF + (f4 * 4 + 0) * 97 + row] = kv.x;
                buf[WOFF + (f4 * 4 + 1) * 97 + row] = kv.y;
                buf[WOFF + (f4 * 4 + 2) * 97 + row] = kv.z;
                buf[WOFF + (f4 * 4 + 3) * 97 + row] = kv.w;
            }
        }
        __syncthreads();
        #pragma unroll 8
        for (int kk = 0; kk < 32; ++kk) {
            float qr[3], kr[6];
            #pragma unroll
            for (int i = 0; i < 3; i++)
                qr[i] = buf[kk * 49 + ty * 3 + i];
            #pragma unroll
            for (int j = 0; j < 6; j++)
                kr[j] = buf[WOFF + kk * 97 + tx * 6 + j];
            #pragma unroll
            for (int i = 0; i < 3; i++)
                #pragma unroll
                for (int j = 0; j < 6; j++)
                    acc[i][j] = fmaf(qr[i], kr[j], acc[i][j]);
        }
    }
    __syncthreads();

    const float scale = 0.015625f;
    #pragma unroll
    for (int i = 0; i < 3; i++) {
        const int dl = ty * 3 + i;
        #pragma unroll
        for (int j = 0; j < 6; j++) {
            const int e = tx * 6 + j;
            float v = acc[i][j] + bqs[dl] * us_[e] + bks[e] * ws_[dl]
                      + 4096.f * bqs[dl] * bks[e];
            buf[dl * 96 + e] = v * scale;
        }
    }
    __syncthreads();

    const int wid = tid >> 5, lane = tid & 31;
    for (int r = wid; r < 48; r += 8) {
        float v0 = buf[r * 96 + lane];
        float v1 = buf[r * 96 + 32 + lane];
        float v2 = buf[r * 96 + 64 + lane];
        float m = fmaxf(v0, fmaxf(v1, v2));
        #pragma unroll
        for (int off = 16; off > 0; off >>= 1)
            m = fmaxf(m, __shfl_xor_sync(0xffffffffu, m, off));
        float e0 = expf(v0 - m), e1 = expf(v1 - m), e2 = expf(v2 - m);
        float s = e0 + e1 + e2;
        #pragma unroll
        for (int off = 16; off > 0; off >>= 1)
            s += __shfl_xor_sync(0xffffffffu, s, off);
        const float inv = 1.f / s;
        float* arow = g_attn + ((size_t)bh * 96 + yh * 48 + r) * 96;
        arow[lane]      = e0 * inv;
        arow[lane + 32] = e1 * inv;
        arow[lane + 64] = e2 * inv;
    }
}

// ---------------------------------------------------------------------------
// MT_b[c, h*96+d] = sum_e A_bh[d,e] Wv[h*96+e, c]  (fp16 hi only); grid (6,128)
// ---------------------------------------------------------------------------
__global__ __launch_bounds__(256)
void mt_kernel(const float* __restrict__ w_qkv, const float* __restrict__ b_qkv)
{
    const int c0 = blockIdx.x * 128;
    const int bh = blockIdx.y;
    const int b = bh >> 3, h = bh & 7;

    __shared__ float As[96 * 97];
    __shared__ float Ws[16 * 132];
    __shared__ float bvs[96];

    const int tid = threadIdx.x;
    const int tx = tid & 15;
    const int ty = tid >> 4;

    const float* asrc = g_attn + (size_t)bh * 9216;
    for (int id = tid; id < 9216; id += 256) {
        const int r = id / 96, c = id - r * 96;
        As[r * 97 + c] = asrc[id];
    }
    if (tid < 96) bvs[tid] = b_qkv[2 * CC + h * DD + tid];
    __syncthreads();

    if (blockIdx.x == 0 && tid < 96) {
        float rv = 0.f;
        #pragma unroll 4
        for (int e = 0; e < 96; ++e) rv += As[tid * 97 + e] * bvs[e];
        g_r[b * CC + h * DD + tid] = rv;
    }

    const float* Wv = w_qkv + (size_t)(2 * CC + h * DD) * CC;
    __half* MTh = g_MThi + (size_t)b * GSZ;

    float acc[8][6];
    #pragma unroll
    for (int i = 0; i < 8; i++)
        #pragma unroll
        for (int j = 0; j < 6; j++) acc[i][j] = 0.f;

    for (int e0 = 0; e0 < 96; e0 += 16) {
        if (e0) __syncthreads();
        #pragma unroll
        for (int t = 0; t < 2; ++t) {
            const int id = tid + t * 256;
            const int e = id >> 5, f4 = id & 31;
            float4 v = *(const float4*)(Wv + (size_t)(e0 + e) * CC + c0 + f4 * 4);
            *(float4*)&Ws[e * 132 + f4 * 4] = v;
        }
        __syncthreads();
        #pragma unroll
        for (int e = 0; e < 16; ++e) {
            float vv[8], aa[6];
            #pragma unroll
            for (int i = 0; i < 8; i++) vv[i] = Ws[e * 132 + ty * 8 + i];
            #pragma unroll
            for (int j = 0; j < 6; j++) aa[j] = As[(tx * 6 + j) * 97 + e0 + e];
            #pragma unroll
            for (int i = 0; i < 8; i++)
                #pragma unroll
                for (int j = 0; j < 6; j++)
                    acc[i][j] = fmaf(vv[i], aa[j], acc[i][j]);
        }
    }
    #pragma unroll
    for (int i = 0; i < 8; i++) {
        const int c = c0 + ty * 8 + i;
        const size_t base = (size_t)c * CC + h * DD + tx * 6;
        #pragma unroll
        for (int j = 0; j < 6; j += 2) {
            *(ushort2*)(MTh + base + j) =
                make_ushort2(hfu(__float2half_rn(acc[i][j])),
                             hfu(__float2half_rn(acc[i][j + 1])));
        }
    }
}

// ---------------------------------------------------------------------------
extern "C" void kernel_launch(void* const* d_in, const int* in_sizes, int n_in,
                              void* d_out, int out_size)
{
    const float* x      = (const float*)d_in[0];
    const float* w_qkv  = (const float*)d_in[1];
    const float* b_qkv  = (const float*)d_in[2];
    const float* w_proj = (const float*)d_in[3];
    const float* b_proj = (const float*)d_in[4];
    float*       out    = (float*)d_out;

    cudaFuncSetAttribute(tgemm_kernel<0>,
                         cudaFuncAttributeMaxDynamicSharedMemorySize, SMEM_012);
    cudaFuncSetAttribute(tgemm_kernel<1>,
                         cudaFuncAttributeMaxDynamicSharedMemorySize, SMEM_012);
    cudaFuncSetAttribute(tgemm_kernel<2>,
                         cudaFuncAttributeMaxDynamicSharedMemorySize, SMEM_3);
    cudaFuncSetAttribute(tgemm_kernel<3>,
                         cudaFuncAttributeMaxDynamicSharedMemorySize, SMEM_3);

    // 0) splits + transposed splits + fused column sums; weight splits + colsum
    transpose_split_kernel<<<dim3(12, 1024), 256>>>(x);
    prep_kernel<<<1168, 256>>>((const float4*)w_qkv, (const float4*)w_proj);

    // 1) G partials (2-PASS, K-split x4, diag dedup) + reduce/split/mirror (x4)
    tgemm_kernel<0><<<dim3(21, KSPL, BB), 256, SMEM_012>>>(nullptr);
    greduce_kernel<<<dim3(21, BB, 4), 256>>>();

    // 2) T_b = Wq @ G_b  (3-pass)
    tgemm_kernel<1><<<dim3(6, 6, BB), 256, SMEM_012>>>(nullptr);

    // 3) rank-1 correction dots, logits + softmax (d-split x2)
    uw_kernel<<<dim3(192, BB), 256>>>(w_qkv);
    logits_kernel<<<dim3(BB * HH, 2), 256>>>(w_qkv, b_qkv);

    // 4) MT_b = (A @ Wv)^T stacked (fp16 hi only); r_bh
    mt_kernel<<<dim3(6, BB * HH), 256>>>(w_qkv, b_qkv);

    // 5) P_b = Wp_hi @ MT_hi (single-pass, 5-stage); fused output bias
    biasf_kernel<<<dim3(96, BB), 256>>>(w_proj, b_proj);
    tgemm_kernel<2><<<dim3(6, 6, BB), 256, SMEM_3>>>(nullptr);

    // 6) out = Xhi @ Phi^T + biasf   (single-pass fp16, 5-stage)
    tgemm_kernel<3><<<dim3(6, 512, 1), 256, SMEM_3>>>(out);
}

// round 16
// speedup vs baseline: 1.1832x; 1.0423x over previous
#include <cuda_runtime.h>
#include <cuda_fp16.h>
#include <cstdint>

// Problem constants
#define BB   16
#define NT   4096
#define CC   768
#define HH   8
#define DD   96
#define MM   (BB * NT)          // 65536
#define GSZ  (768 * 768)        // 589824
#define KSPL 4                  // K-split for the G GEMM

// ---------------------------------------------------------------------------
// Scratch (__device__ globals)
// ---------------------------------------------------------------------------
__device__ __half g_xhi[(size_t)MM * CC];
__device__ __half g_xThi[(size_t)MM * CC], g_xTlo[(size_t)MM * CC]; // [b,c,n]
__device__ float g_Gpart[(size_t)BB * KSPL * 21 * 16384];           // fp32 partials
__device__ __half g_Ghi[BB * GSZ], g_Glo[BB * GSZ];
__device__ float g_T[BB * GSZ];
__device__ float g_attn[BB * HH * DD * DD];
__device__ __half g_MThi[BB * GSZ];                     // [b, c, h*96+d]
__device__ __half g_Phi[BB * GSZ];
__device__ __half g_wqh[GSZ];
__device__ __half g_wph[GSZ];
__device__ float g_s[BB * CC];
__device__ float g_part2[1024 * CC];                    // per-64-row-block colsums
__device__ float g_U[BB * 1536];
__device__ float g_r[BB * CC];
__device__ float g_biasf[BB * CC];

// ---------------------------------------------------------------------------
// PTX helpers (target-agnostic)
// ---------------------------------------------------------------------------
__device__ __forceinline__ uint32_t smem_u32(const void* p) {
    uint32_t a;
    asm("{ .reg .u64 t; cvta.to.shared.u64 t, %1; cvt.u32.u64 %0, t; }"
        : "=r"(a) : "l"(p));
    return a;
}
__device__ __forceinline__ void ldsm_x4(uint32_t* r, uint32_t addr) {
    asm volatile("ldmatrix.sync.aligned.m8n8.x4.shared.b16 {%0,%1,%2,%3}, [%4];"
                 : "=r"(r[0]), "=r"(r[1]), "=r"(r[2]), "=r"(r[3]) : "r"(addr));
}
__device__ __forceinline__ void mma16816(float* c, const uint32_t* a, const uint32_t* b) {
    asm volatile(
        "mma.sync.aligned.m16n8k16.row.col.f32.f16.f16.f32 "
        "{%0,%1,%2,%3}, {%4,%5,%6,%7}, {%8,%9}, {%0,%1,%2,%3};"
        : "+f"(c[0]), "+f"(c[1]), "+f"(c[2]), "+f"(c[3])
        : "r"(a[0]), "r"(a[1]), "r"(a[2]), "r"(a[3]), "r"(b[0]), "r"(b[1]));
}
__device__ __forceinline__ void cp16(uint32_t dst, const void* src) {
    asm volatile("cp.async.cg.shared.global [%0], [%1], 16;"
                 :: "r"(dst), "l"(src) : "memory");
}
__device__ __forceinline__ void cp_commit() {
    asm volatile("cp.async.commit_group;" ::: "memory");
}
template <int N>
__device__ __forceinline__ void cp_wait() {
    asm volatile("cp.async.wait_group %0;" :: "n"(N) : "memory");
}
__device__ __forceinline__ void split1(float v, __half& h, __half& l) {
    h = __float2half_rn(v);
    l = __float2half_rn(v - __half2float(h));
}
__device__ __forceinline__ ushort hfu(__half v) { return __half_as_ushort(v); }

// ---------------------------------------------------------------------------
// transpose_split: x -> row-major hi, per-batch transposed hi/lo,
// AND per-block column partial sums (fused colsum).
// ---------------------------------------------------------------------------
__global__ __launch_bounds__(256)
void transpose_split_kernel(const float* __restrict__ x)
{
    __shared__ float tile[64 * 65];
    __shared__ float colp[4][64];
    const int tid = threadIdx.x;
    const int C0 = blockIdx.x * 64;
    const int R0 = blockIdx.y * 64;

    #pragma unroll
    for (int t = 0; t < 4; ++t) {
        const int id = tid + t * 256;
        const int r = id >> 4, f4 = id & 15;
        float4 v = *(const float4*)(x + (size_t)(R0 + r) * CC + C0 + f4 * 4);
        tile[r * 65 + f4 * 4 + 0] = v.x;
        tile[r * 65 + f4 * 4 + 1] = v.y;
        tile[r * 65 + f4 * 4 + 2] = v.z;
        tile[r * 65 + f4 * 4 + 3] = v.w;
    }
    __syncthreads();

    {
        const int c = tid & 63, q = tid >> 6;
        float s = 0.f;
        #pragma unroll
        for (int r = 0; r < 16; ++r) s += tile[(q * 16 + r) * 65 + c];
        colp[q][c] = s;
    }
    __syncthreads();
    if (tid < 64)
        g_part2[(size_t)blockIdx.y * CC + C0 + tid] =
            colp[0][tid] + colp[1][tid] + colp[2][tid] + colp[3][tid];

    #pragma unroll
    for (int t = 0; t < 2; ++t) {
        const int id = tid + t * 256;
        const int r = id >> 3, g = id & 7;
        ushort h[8];
        #pragma unroll
        for (int j = 0; j < 8; j++)
            h[j] = hfu(__float2half_rn(tile[r * 65 + g * 8 + j]));
        uint4 uh;
        uh.x = h[0] | (h[1] << 16); uh.y = h[2] | (h[3] << 16);
        uh.z = h[4] | (h[5] << 16); uh.w = h[6] | (h[7] << 16);
        const size_t off = (size_t)(R0 + r) * CC + C0 + g * 8;
        *(uint4*)(g_xhi + off) = uh;
    }

    const int bb = R0 >> 12;
    const int n0 = R0 & 4095;
    #pragma unroll
    for (int t = 0; t < 2; ++t) {
        const int id = tid + t * 256;
        const int c = id >> 3, g = id & 7;
        ushort h[8], l[8];
        #pragma unroll
        for (int j = 0; j < 8; j++) {
            __half hb, lb; split1(tile[(g * 8 + j) * 65 + c], hb, lb);
            h[j] = hfu(hb); l[j] = hfu(lb);
        }
        uint4 uh, ul;
        uh.x = h[0] | (h[1] << 16); uh.y = h[2] | (h[3] << 16);
        uh.z = h[4] | (h[5] << 16); uh.w = h[6] | (h[7] << 16);
        ul.x = l[0] | (l[1] << 16); ul.y = l[2] | (l[3] << 16);
        ul.z = l[4] | (l[5] << 16); ul.w = l[6] | (l[7] << 16);
        const size_t off = ((size_t)bb * CC + C0 + c) * NT + n0 + g * 8;
        *(uint4*)(g_xThi + off) = uh;
        *(uint4*)(g_xTlo + off) = ul;
    }
}

// ---------------------------------------------------------------------------
// prep: blocks [0,576) wq hi split; [576,1152) wp hi split;
//       blocks [1152,1168) colsum reduction.
// ---------------------------------------------------------------------------
__global__ __launch_bounds__(256)
void prep_kernel(const float4* __restrict__ wq, const float4* __restrict__ wp)
{
    const int blk = blockIdx.x;
    const int tid = threadIdx.x;
    if (blk < 1152) {
        const bool isq = (blk < 576);
        const int j = (isq ? blk : blk - 576) * 256 + tid;
        float4 v = isq ? wq[j] : wp[j];
        ushort h[4];
        h[0] = hfu(__float2half_rn(v.x));
        h[1] = hfu(__float2half_rn(v.y));
        h[2] = hfu(__float2half_rn(v.z));
        h[3] = hfu(__float2half_rn(v.w));
        ((ushort4*)(isq ? g_wqh : g_wph))[j] = make_ushort4(h[0], h[1], h[2], h[3]);
    } else {
        const int b = blk - 1152;
        #pragma unroll
        for (int p = 0; p < 3; ++p) {
            const int c = p * 256 + tid;
            float s = 0.f;
            for (int k = 0; k < 64; ++k)
                s += g_part2[(size_t)(b * 64 + k) * CC + c];
            g_s[b * CC + c] = s;
        }
    }
}

// ---------------------------------------------------------------------------
// U[b][row] = dot(w_qkv[row], s_b), rows 0..1535
// ---------------------------------------------------------------------------
__global__ __launch_bounds__(256)
void uw_kernel(const float* __restrict__ w_qkv)
{
    __shared__ float ss[CC];
    const int b = blockIdx.y, tid = threadIdx.x;
    #pragma unroll
    for (int p = 0; p < 3; ++p) ss[p * 256 + tid] = g_s[b * CC + p * 256 + tid];
    __syncthreads();
    const int row = blockIdx.x * 8 + (tid >> 5);
    const int lane = tid & 31;
    const float* wr = w_qkv + (size_t)row * CC;
    float acc = 0.f;
    #pragma unroll
    for (int k = 0; k < 24; ++k) acc += wr[lane + k * 32] * ss[lane + k * 32];
    #pragma unroll
    for (int off = 16; off > 0; off >>= 1)
        acc += __shfl_xor_sync(0xffffffffu, acc, off);
    if (lane == 0) g_U[b * 1536 + row] = acc;
}

// ---------------------------------------------------------------------------
// biasf[b][j] = b_proj[j] + dot(w_proj[j], r_b)
// ---------------------------------------------------------------------------
__global__ __launch_bounds__(256)
void biasf_kernel(const float* __restrict__ w_proj, const float* __restrict__ b_proj)
{
    __shared__ float rr[CC];
    const int b = blockIdx.y, tid = threadIdx.x;
    #pragma unroll
    for (int p = 0; p < 3; ++p) rr[p * 256 + tid] = g_r[b * CC + p * 256 + tid];
    __syncthreads();
    const int j = blockIdx.x * 8 + (tid >> 5);
    const int lane = tid & 31;
    const float* wr = w_proj + (size_t)j * CC;
    float acc = 0.f;
    #pragma unroll
    for (int k = 0; k < 24; ++k) acc += wr[lane + k * 32] * rr[lane + k * 32];
    #pragma unroll
    for (int off = 16; off > 0; off >>= 1)
        acc += __shfl_xor_sync(0xffffffffu, acc, off);
    if (lane == 0) g_biasf[b * CC + j] = b_proj[j] + acc;
}

// ---------------------------------------------------------------------------
// HMMA fp16-split GEMM, templated on MODE.
//   MODE 0: Gpart = Xhi^T @ (Xhi + Xlo)  (2-PASS, K-split, fp32 out)
//           grid (21, KSPL, BB); diag: Bh deduped onto A slot, Bl in slot 1
//   MODE 1: T_b = Wq_hi @ (Ghi + Glo)    (2-PASS, fp32 out)
//   MODE 2: P_b = Wp_hi @ MT_hi  (K=768, 1-pass, fp16 hi out, 5-stage)
//   MODE 3: out = X_hi @ P_hi^T + biasf  (K=768, 1-pass, 5-stage)
// ---------------------------------------------------------------------------
#define SROW 80
#define TILE_B (128 * SROW)
#define SMEM_012 (2 * 4 * TILE_B)   // 81920 (modes 0,1)
#define SMEM_3   (5 * 2 * TILE_B)   // 102400 (modes 2,3)

template <int MODE>
__global__ __launch_bounds__(256, 2)
void tgemm_kernel(float* __restrict__ Cp)
{
    constexpr bool SINGLE = (MODE >= 2);
    constexpr int NTILES = SINGLE ? 2 : 4;
    constexpr int NSTAGE = SINGLE ? 5 : 2;
    constexpr int STAGE_B = NTILES * TILE_B;

    int bm = blockIdx.y, bn = blockIdx.x;
    int b = blockIdx.z;
    int ksplit = 0;
    if (MODE == 0) {
        int t = blockIdx.x;
        bm = 0;
        while (t >= 6 - bm) { t -= 6 - bm; bm++; }
        bn = bm + t;
        ksplit = blockIdx.y;
    }
    const bool diag = (MODE == 0) && (bm == bn);

    const __half *Ah, *Wh, *Wl = nullptr;
    constexpr int KROW  = (MODE == 0) ? 4096 : 768;
    constexpr int KITER = (MODE == 0) ? 1024 : 768;

    if (MODE == 0) {
        const size_t ab = ((size_t)b * CC + bm * 128) * NT + ksplit * KITER;
        const size_t wb = ((size_t)b * CC + bn * 128) * NT + ksplit * KITER;
        Ah = g_xThi + ab;                    // A = Xhi(bm) only (2-pass)
        Wh = g_xThi + wb; Wl = g_xTlo + wb;  // B = Xhi(bn), Xlo(bn)
    } else if (MODE == 1) {
        Ah = g_wqh + (size_t)bm * 128 * CC;  // A = Wq_hi only (2-pass)
        const size_t wb = (size_t)b * GSZ + (size_t)bn * 128 * CC;
        Wh = g_Ghi + wb; Wl = g_Glo + wb;
    } else if (MODE == 2) {
        Ah = g_wph + (size_t)bm * 128 * CC;
        Wh = g_MThi + (size_t)b * GSZ + (size_t)bn * 128 * CC;
    } else {
        b = bm >> 5;
        Ah = g_xhi + (size_t)bm * 128 * CC;
        Wh = g_Phi + (size_t)b * GSZ + (size_t)bn * 128 * CC;
    }

    extern __shared__ char smem[];
    const uint32_t ubase = smem_u32(smem);

    const int tid  = threadIdx.x;
    const int wid  = tid >> 5;
    const int lane = tid & 31;
    const int wm   = wid & 1;
    const int wn   = wid >> 1;

    const int cr = tid >> 2;
    const int cg = tid & 3;

    const uint32_t boff = SINGLE ? TILE_B : (diag ? 0u : 2u * TILE_B);

    #define ISSUE(s) do { \
        const uint32_t sb_ = ubase + ((s) % NSTAGE) * STAGE_B; \
        const int kof_ = (s) * 32; \
        _Pragma("unroll") \
        for (int t_ = 0; t_ < 2; ++t_) { \
            const int r_ = cr + t_ * 64; \
            const size_t off_ = (size_t)r_ * KROW + kof_ + cg * 8; \
            const uint32_t d_ = sb_ + r_ * SROW + cg * 16; \
            cp16(d_ + 0 * TILE_B, Ah + off_); \
            if (SINGLE) { \
                cp16(d_ + TILE_B, Wh + off_); \
            } else if (diag) { \
                cp16(d_ + 1 * TILE_B, Wl + off_); \
            } else { \
                cp16(d_ + 2 * TILE_B, Wh + off_); \
                cp16(d_ + 3 * TILE_B, Wl + off_); \
            } \
        } \
        cp_commit(); \
    } while (0)

    float acc[4][4][4];
    #pragma unroll
    for (int i = 0; i < 4; i++)
        #pragma unroll
        for (int j = 0; j < 4; j++)
            #pragma unroll
            for (int q = 0; q < 4; q++) acc[i][j][q] = 0.f;

    const int laneRA = lane & 15;
    const int laneGA = lane >> 4;
    const int laneRB = (lane & 7) | ((lane >> 4) << 3);
    const int laneGB = (lane >> 3) & 1;

    const int NK = KITER >> 5;

    if (SINGLE) { ISSUE(0); ISSUE(1); ISSUE(2); ISSUE(3); }
    else        { ISSUE(0); ISSUE(1); }

    for (int kb = 0; kb < NK; ++kb) {
        if (SINGLE) {
            if (kb + 4 <= NK) cp_wait<3>();
            else if (kb + 3 <= NK) cp_wait<2>();
            else if (kb + 2 <= NK) cp_wait<1>();
            else cp_wait<0>();
            __syncthreads();
            if (kb + 4 < NK) ISSUE(kb + 4);   // slot (kb-1)%5: readers done
        } else {
            if (kb + 1 < NK) cp_wait<1>(); else cp_wait<0>();
            __syncthreads();
        }

        const uint32_t sb = ubase + (kb % NSTAGE) * STAGE_B;
        const uint32_t aBase = sb + (wm * 64 + laneRA) * SROW + laneGA * 16;
        const uint32_t bBase = sb + boff + (wn * 32 + laneRB) * SROW + laneGB * 16;

        #pragma unroll
        for (int ks = 0; ks < 2; ++ks) {
            const uint32_t ko = ks * 32;
            uint32_t bh[4][2], bl[4][2];
            #pragma unroll
            for (int fp = 0; fp < 2; fp++) {
                uint32_t q[4];
                ldsm_x4(q, bBase + fp * (16 * SROW) + ko);
                bh[2 * fp][0] = q[0]; bh[2 * fp][1] = q[1];
                bh[2 * fp + 1][0] = q[2]; bh[2 * fp + 1][1] = q[3];
                if (!SINGLE) {
                    ldsm_x4(q, bBase + TILE_B + fp * (16 * SROW) + ko);
                    bl[2 * fp][0] = q[0]; bl[2 * fp][1] = q[1];
                    bl[2 * fp + 1][0] = q[2]; bl[2 * fp + 1][1] = q[3];
                }
            }
            #pragma unroll
            for (int fm = 0; fm < 4; fm++) {
                uint32_t ah[4];
                ldsm_x4(ah, aBase + fm * (16 * SROW) + ko);
                #pragma unroll
                for (int fn = 0; fn < 4; fn++) {
                    mma16816(acc[fm][fn], ah, bh[fn]);
                    if (!SINGLE) mma16816(acc[fm][fn], ah, bl[fn]);
                }
            }
        }

        if (!SINGLE && kb + 2 < NK) {
            __syncthreads();      // all warps done reading this buffer
            ISSUE(kb + 2);
        }
    }

    const int gid4 = lane >> 2;
    const int tig  = lane & 3;

    if (MODE == 1 || MODE == 3) {
        float* C = (MODE == 1) ? (g_T + (size_t)b * GSZ) : Cp;
        const float* bias = (MODE == 3) ? (g_biasf + b * CC) : nullptr;
        #pragma unroll
        for (int fm = 0; fm < 4; fm++) {
            const int m0 = bm * 128 + wm * 64 + fm * 16 + gid4;
            #pragma unroll
            for (int fn = 0; fn < 4; fn++) {
                const int col = bn * 128 + wn * 32 + fn * 8 + tig * 2;
                float bx = 0.f, by = 0.f;
                if (MODE == 3) { bx = bias[col]; by = bias[col + 1]; }
                float2 o;
                o.x = acc[fm][fn][0] + bx; o.y = acc[fm][fn][1] + by;
                *(float2*)(C + (size_t)m0 * CC + col) = o;
                o.x = acc[fm][fn][2] + bx; o.y = acc[fm][fn][3] + by;
                *(float2*)(C + (size_t)(m0 + 8) * CC + col) = o;
            }
        }
    } else if (MODE == 0) {
        float* P = g_Gpart + (((size_t)b * KSPL + ksplit) * 21 + blockIdx.x) * 16384;
        #pragma unroll
        for (int fm = 0; fm < 4; fm++) {
            const int m0 = wm * 64 + fm * 16 + gid4;
            #pragma unroll
            for (int fn = 0; fn < 4; fn++) {
                const int col = wn * 32 + fn * 8 + tig * 2;
                *(float2*)(P + (size_t)m0 * 128 + col) =
                    make_float2(acc[fm][fn][0], acc[fm][fn][1]);
                *(float2*)(P + (size_t)(m0 + 8) * 128 + col) =
                    make_float2(acc[fm][fn][2], acc[fm][fn][3]);
            }
        }
    } else {   // MODE 2: P hi only
        __half* Hi = g_Phi + (size_t)b * GSZ;
        #pragma unroll
        for (int fm = 0; fm < 4; fm++) {
            const int m0 = bm * 128 + wm * 64 + fm * 16 + gid4;
            #pragma unroll
            for (int fn = 0; fn < 4; fn++) {
                const int col = bn * 128 + wn * 32 + fn * 8 + tig * 2;
                *(ushort2*)(Hi + (size_t)m0 * CC + col) =
                    make_ushort2(hfu(__float2half_rn(acc[fm][fn][0])),
                                 hfu(__float2half_rn(acc[fm][fn][1])));
                *(ushort2*)(Hi + (size_t)(m0 + 8) * CC + col) =
                    make_ushort2(hfu(__float2half_rn(acc[fm][fn][2])),
                                 hfu(__float2half_rn(acc[fm][fn][3])));
            }
        }
    }
    #undef ISSUE
}

// ---------------------------------------------------------------------------
// greduce: sum KSPL partials of one 32-row QUARTER of a G tile, split to fp16
// hi/lo, write tile + symmetric mirror. grid (21, 16, 4), block 256.
// ---------------------------------------------------------------------------
__global__ __launch_bounds__(256)
void greduce_kernel()
{
    __shared__ float s[32][132];
    int t = blockIdx.x;
    const int b = blockIdx.y;
    const int qz = blockIdx.z;           // 0..3 quarter (32 rows)
    int bm = 0;
    while (t >= 6 - bm) { t -= 6 - bm; bm++; }
    const int bn = bm + t;
    const int tid = threadIdx.x;

    const float* P0 = g_Gpart + (((size_t)b * KSPL) * 21 + blockIdx.x) * 16384;
    const float* P1 = P0 + (size_t)21 * 16384;
    const float* P2 = P1 + (size_t)21 * 16384;
    const float* P3 = P2 + (size_t)21 * 16384;
    __half* Hi = g_Ghi + (size_t)b * GSZ;
    __half* Lo = g_Glo + (size_t)b * GSZ;

    const int rbase = qz * 32;
    #pragma unroll
    for (int e4 = tid; e4 < 1024; e4 += 256) {
        const int r = e4 >> 5, c4 = e4 & 31;
        const size_t o = (size_t)(rbase + r) * 128 + c4 * 4;
        float4 a = *(const float4*)(P0 + o);
        float4 bb = *(const float4*)(P1 + o);
        float4 c = *(const float4*)(P2 + o);
        float4 d = *(const float4*)(P3 + o);
        s[r][c4 * 4 + 0] = a.x + bb.x + c.x + d.x;
        s[r][c4 * 4 + 1] = a.y + bb.y + c.y + d.y;
        s[r][c4 * 4 + 2] = a.z + bb.z + c.z + d.z;
        s[r][c4 * 4 + 3] = a.w + bb.w + c.w + d.w;
    }
    __syncthreads();

    {
        const int r = tid >> 3, cb = (tid & 7) * 16;
        const size_t rowo = (size_t)(bm * 128 + rbase + r) * CC + bn * 128 + cb;
        #pragma unroll
        for (int k = 0; k < 16; k += 8) {
            ushort hh[8], ll[8];
            #pragma unroll
            for (int j = 0; j < 8; ++j) {
                __half hb, lb; split1(s[r][cb + k + j], hb, lb);
                hh[j] = hfu(hb); ll[j] = hfu(lb);
            }
            uint4 uh, ul;
            uh.x = hh[0] | (hh[1] << 16); uh.y = hh[2] | (hh[3] << 16);
            uh.z = hh[4] | (hh[5] << 16); uh.w = hh[6] | (hh[7] << 16);
            ul.x = ll[0] | (ll[1] << 16); ul.y = ll[2] | (ll[3] << 16);
            ul.z = ll[4] | (ll[5] << 16); ul.w = ll[6] | (ll[7] << 16);
            *(uint4*)(Hi + rowo + k) = uh;
            *(uint4*)(Lo + rowo + k) = ul;
        }
    }
    if (bm != bn) {
        const int j = tid >> 1, cb = (tid & 1) * 16;
        const size_t rowo = (size_t)(bn * 128 + j) * CC + bm * 128 + rbase + cb;
        #pragma unroll
        for (int k = 0; k < 16; k += 8) {
            ushort hh[8], ll[8];
            #pragma unroll
            for (int jj = 0; jj < 8; ++jj) {
                __half hb, lb; split1(s[cb + k + jj][j], hb, lb);
                hh[jj] = hfu(hb); ll[jj] = hfu(lb);
            }
            uint4 uh, ul;
            uh.x = hh[0] | (hh[1] << 16); uh.y = hh[2] | (hh[3] << 16);
            uh.z = hh[4] | (hh[5] << 16); uh.w = hh[6] | (hh[7] << 16);
            ul.x = ll[0] | (ll[1] << 16); ul.y = ll[2] | (ll[3] << 16);
            ul.z = ll[4] | (ll[5] << 16); ul.w = ll[6] | (ll[7] << 16);
            *(uint4*)(Hi + rowo + k) = uh;
            *(uint4*)(Lo + rowo + k) = ul;
        }
    }
}

// ---------------------------------------------------------------------------
// logits + softmax per (b,h), 2 d-halves. grid (128, 2).
// ---------------------------------------------------------------------------
#define WOFF 1600
__global__ __launch_bounds__(256)
void logits_kernel(const float* __restrict__ w_qkv, const float* __restrict__ b_qkv)
{
    const int bh = blockIdx.x;
    const int yh = blockIdx.y;
    const int b = bh >> 3, h = bh & 7;

    __shared__ float buf[WOFF + 3104];
    __shared__ float bqs[48], ws_[48], bks[96], us_[96];

    const int tid = threadIdx.x;
    const int tx = tid & 15;
    const int ty = tid >> 4;

    if (tid < 48) {
        bqs[tid] = b_qkv[h * DD + yh * 48 + tid];
        ws_[tid] = g_U[b * 1536 + h * DD + yh * 48 + tid];
    }
    if (tid < 96) {
        bks[tid] = b_qkv[CC + h * DD + tid];
        us_[tid] = g_U[b * 1536 + CC + h * DD + tid];
    }

    const float* Tb = g_T + (size_t)b * GSZ + (size_t)(h * DD + yh * 48) * CC;
    const float* Wk = w_qkv + (size_t)(CC + h * DD) * CC;

    float acc[3][6];
    #pragma unroll
    for (int i = 0; i < 3; i++)
        #pragma unroll
        for (int j = 0; j < 6; j++) acc[i][j] = 0.f;

    for (int c0 = 0; c0 < CC; c0 += 32) {
        __syncthreads();
        for (int id = tid; id < 384 + 768; id += 256) {
            if (id < 384) {
                const int row = id >> 3, f4 = id & 7;
                float4 tv = *(const float4*)(Tb + (size_t)row * CC + c0 + f4 * 4);
                buf[(f4 * 4 + 0) * 49 + row] = tv.x;
                buf[(f4 * 4 + 1) * 49 + row] = tv.y;
                buf[(f4 * 4 + 2) * 49 + row] = tv.z;
                buf[(f4 * 4 + 3) * 49 + row] = tv.w;
            } else {
                const int id2 = id - 384;
                const int row = id2 >> 3, f4 = id2 & 7;
                float4 kv = *(const float4*)(Wk + (size_t)row * CC + c0 + f4 * 4);
                buf[WOFF + (f4 * 4 + 0) * 97 + row] = kv.x;
                buf[WOFF + (f4 * 4 + 1) * 97 + row] = kv.y;
                buf[WOFF + (f4 * 4 + 2) * 97 + row] = kv.z;
                buf[WOFF + (f4 * 4 + 3) * 97 + row] = kv.w;
            }
        }
        __syncthreads();
        #pragma unroll 8
        for (int kk = 0; kk < 32; ++kk) {
            float qr[3], kr[6];
            #pragma unroll
            for (int i = 0; i < 3; i++)
                qr[i] = buf[kk * 49 + ty * 3 + i];
            #pragma unroll
            for (int j = 0; j < 6; j++)
                kr[j] = buf[WOFF + kk * 97 + tx * 6 + j];
            #pragma unroll
            for (int i = 0; i < 3; i++)
                #pragma unroll
                for (int j = 0; j < 6; j++)
                    acc[i][j] = fmaf(qr[i], kr[j], acc[i][j]);
        }
    }
    __syncthreads();

    const float scale = 0.015625f;
    #pragma unroll
    for (int i = 0; i < 3; i++) {
        const int dl = ty * 3 + i;
        #pragma unroll
        for (int j = 0; j < 6; j++) {
            const int e = tx * 6 + j;
            float v = acc[i][j] + bqs[dl] * us_[e] + bks[e] * ws_[dl]
                      + 4096.f * bqs[dl] * bks[e];
            buf[dl * 96 + e] = v * scale;
        }
    }
    __syncthreads();

    const int wid = tid >> 5, lane = tid & 31;
    for (int r = wid; r < 48; r += 8) {
        float v0 = buf[r * 96 + lane];
        float v1 = buf[r * 96 + 32 + lane];
        float v2 = buf[r * 96 + 64 + lane];
        float m = fmaxf(v0, fmaxf(v1, v2));
        #pragma unroll
        for (int off = 16; off > 0; off >>= 1)
            m = fmaxf(m, __shfl_xor_sync(0xffffffffu, m, off));
        float e0 = expf(v0 - m), e1 = expf(v1 - m), e2 = expf(v2 - m);
        float s = e0 + e1 + e2;
        #pragma unroll
        for (int off = 16; off > 0; off >>= 1)
            s += __shfl_xor_sync(0xffffffffu, s, off);
        const float inv = 1.f / s;
        float* arow = g_attn + ((size_t)bh * 96 + yh * 48 + r) * 96;
        arow[lane]      = e0 * inv;
        arow[lane + 32] = e1 * inv;
        arow[lane + 64] = e2 * inv;
    }
}

// ---------------------------------------------------------------------------
// MT_b[c, h*96+d] = sum_e A_bh[d,e] Wv[h*96+e, c]  (fp16 hi only); grid (6,128)
// ---------------------------------------------------------------------------
__global__ __launch_bounds__(256)
void mt_kernel(const float* __restrict__ w_qkv, const float* __restrict__ b_qkv)
{
    const int c0 = blockIdx.x * 128;
    const int bh = blockIdx.y;
    const int b = bh >> 3, h = bh & 7;

    __shared__ float As[96 * 97];
    __shared__ float Ws[16 * 132];
    __shared__ float bvs[96];

    const int tid = threadIdx.x;
    const int tx = tid & 15;
    const int ty = tid >> 4;

    const float* asrc = g_attn + (size_t)bh * 9216;
    for (int id = tid; id < 9216; id += 256) {
        const int r = id / 96, c = id - r * 96;
        As[r * 97 + c] = asrc[id];
    }
    if (tid < 96) bvs[tid] = b_qkv[2 * CC + h * DD + tid];
    __syncthreads();

    if (blockIdx.x == 0 && tid < 96) {
        float rv = 0.f;
        #pragma unroll 4
        for (int e = 0; e < 96; ++e) rv += As[tid * 97 + e] * bvs[e];
        g_r[b * CC + h * DD + tid] = rv;
    }

    const float* Wv = w_qkv + (size_t)(2 * CC + h * DD) * CC;
    __half* MTh = g_MThi + (size_t)b * GSZ;

    float acc[8][6];
    #pragma unroll
    for (int i = 0; i < 8; i++)
        #pragma unroll
        for (int j = 0; j < 6; j++) acc[i][j] = 0.f;

    for (int e0 = 0; e0 < 96; e0 += 16) {
        if (e0) __syncthreads();
        #pragma unroll
        for (int t = 0; t < 2; ++t) {
            const int id = tid + t * 256;
            const int e = id >> 5, f4 = id & 31;
            float4 v = *(const float4*)(Wv + (size_t)(e0 + e) * CC + c0 + f4 * 4);
            *(float4*)&Ws[e * 132 + f4 * 4] = v;
        }
        __syncthreads();
        #pragma unroll
        for (int e = 0; e < 16; ++e) {
            float vv[8], aa[6];
            #pragma unroll
            for (int i = 0; i < 8; i++) vv[i] = Ws[e * 132 + ty * 8 + i];
            #pragma unroll
            for (int j = 0; j < 6; j++) aa[j] = As[(tx * 6 + j) * 97 + e0 + e];
            #pragma unroll
            for (int i = 0; i < 8; i++)
                #pragma unroll
                for (int j = 0; j < 6; j++)
                    acc[i][j] = fmaf(vv[i], aa[j], acc[i][j]);
        }
    }
    #pragma unroll
    for (int i = 0; i < 8; i++) {
        const int c = c0 + ty * 8 + i;
        const size_t base = (size_t)c * CC + h * DD + tx * 6;
        #pragma unroll
        for (int j = 0; j < 6; j += 2) {
            *(ushort2*)(MTh + base + j) =
                make_ushort2(hfu(__float2half_rn(acc[i][j])),
                             hfu(__float2half_rn(acc[i][j + 1])));
        }
    }
}

// ---------------------------------------------------------------------------
extern "C" void kernel_launch(void* const* d_in, const int* in_sizes, int n_in,
                              void* d_out, int out_size)
{
    const float* x      = (const float*)d_in[0];
    const float* w_qkv  = (const float*)d_in[1];
    const float* b_qkv  = (const float*)d_in[2];
    const float* w_proj = (const float*)d_in[3];
    const float* b_proj = (const float*)d_in[4];
    float*       out    = (float*)d_out;

    cudaFuncSetAttribute(tgemm_kernel<0>,
                         cudaFuncAttributeMaxDynamicSharedMemorySize, SMEM_012);
    cudaFuncSetAttribute(tgemm_kernel<1>,
                         cudaFuncAttributeMaxDynamicSharedMemorySize, SMEM_012);
    cudaFuncSetAttribute(tgemm_kernel<2>,
                         cudaFuncAttributeMaxDynamicSharedMemorySize, SMEM_3);
    cudaFuncSetAttribute(tgemm_kernel<3>,
                         cudaFuncAttributeMaxDynamicSharedMemorySize, SMEM_3);

    // 0) splits + transposed splits + fused column sums; weight splits + colsum
    transpose_split_kernel<<<dim3(12, 1024), 256>>>(x);
    prep_kernel<<<1168, 256>>>((const float4*)w_qkv, (const float4*)w_proj);

    // 1) G partials (2-PASS, K-split x4, diag dedup) + reduce/split/mirror (x4)
    tgemm_kernel<0><<<dim3(21, KSPL, BB), 256, SMEM_012>>>(nullptr);
    greduce_kernel<<<dim3(21, BB, 4), 256>>>();

    // 2) T_b = Wq_hi @ (Ghi + Glo)  (2-PASS)
    tgemm_kernel<1><<<dim3(6, 6, BB), 256, SMEM_012>>>(nullptr);

    // 3) rank-1 correction dots, logits + softmax (d-split x2)
    uw_kernel<<<dim3(192, BB), 256>>>(w_qkv);
    logits_kernel<<<dim3(BB * HH, 2), 256>>>(w_qkv, b_qkv);

    // 4) MT_b = (A @ Wv)^T stacked (fp16 hi only); r_bh
    mt_kernel<<<dim3(6, BB * HH), 256>>>(w_qkv, b_qkv);

    // 5) P_b = Wp_hi @ MT_hi (single-pass, 5-stage); fused output bias
    biasf_kernel<<<dim3(96, BB), 256>>>(w_proj, b_proj);
    tgemm_kernel<2><<<dim3(6, 6, BB), 256, SMEM_3>>>(nullptr);

    // 6) out = Xhi @ Phi^T + biasf   (single-pass fp16, 5-stage)
    tgemm_kernel<3><<<dim3(6, 512, 1), 256, SMEM_3>>>(out);
}